// round 1
// baseline (speedup 1.0000x reference)
#include <cuda_runtime.h>
#include <math.h>

#define NN   100000
#define EE   1600000
#define GG   128
#define DEMB 300
#define DHID 600
#define DIN  20
#define DOUT 64
#define BN_EPS 1e-5f

// ---------------- scratch (device globals; no allocation allowed) ----------------
__device__ float g_t[(size_t)NN * DHID];    // hidden activations [N,600]
__device__ float g_h[(size_t)NN * DEMB];    // raw (pre-BN) layer output [N,300]
__device__ float g_agg[(size_t)NN * DEMB];  // aggregated messages [N,<=300]
__device__ int   g_rowptr[NN + 1];
__device__ int   g_deg[NN];
__device__ int   g_cursor[NN];
__device__ int   g_csrc[EE];
__device__ float g_esum[NN];
__device__ float g_colsum[DEMB];
__device__ float g_colsq[DEMB];
__device__ float g_a[DEMB];                 // BN fused scale
__device__ float g_c[DEMB];                 // BN fused shift
__device__ float g_pool[GG * DEMB];
__device__ float g_cnt[GG];

// ---------------- preprocessing kernels ----------------
__global__ void k_zero_pre() {
    int i = blockIdx.x * blockDim.x + threadIdx.x;
    if (i < NN) { g_deg[i] = 0; g_cursor[i] = 0; g_esum[i] = 0.f; }
}

__global__ void k_zero_pool() {
    int i = blockIdx.x * blockDim.x + threadIdx.x;
    if (i < GG * DEMB) g_pool[i] = 0.f;
    if (i < GG) g_cnt[i] = 0.f;
}

__global__ void k_zero_stats() {
    int i = threadIdx.x;
    if (i < DEMB) { g_colsum[i] = 0.f; g_colsq[i] = 0.f; }
}

__global__ void k_edge_prep(const int* __restrict__ dst, const float* __restrict__ ef) {
    int e = blockIdx.x * blockDim.x + threadIdx.x;
    if (e < EE) {
        int d = dst[e];
        atomicAdd(&g_deg[d], 1);
        atomicAdd(&g_esum[d], ef[e]);
    }
}

// single-block exclusive scan of g_deg -> g_rowptr
__global__ void k_scan() {
    __shared__ int sh[1024];
    __shared__ int carry;
    if (threadIdx.x == 0) carry = 0;
    __syncthreads();
    for (int base = 0; base < NN; base += 1024) {
        int i = base + threadIdx.x;
        int v = (i < NN) ? g_deg[i] : 0;
        sh[threadIdx.x] = v;
        __syncthreads();
        for (int off = 1; off < 1024; off <<= 1) {
            int t = (threadIdx.x >= off) ? sh[threadIdx.x - off] : 0;
            __syncthreads();
            sh[threadIdx.x] += t;
            __syncthreads();
        }
        if (i < NN) g_rowptr[i] = carry + sh[threadIdx.x] - v;  // exclusive
        __syncthreads();
        if (threadIdx.x == 0) carry += sh[1023];
        __syncthreads();
    }
    if (threadIdx.x == 0) g_rowptr[NN] = carry;
}

__global__ void k_edge_fill(const int* __restrict__ src, const int* __restrict__ dst) {
    int e = blockIdx.x * blockDim.x + threadIdx.x;
    if (e < EE) {
        int d = dst[e];
        int pos = atomicAdd(&g_cursor[d], 1);
        g_csrc[g_rowptr[d] + pos] = src[e];
    }
}

__global__ void k_counts(const int* __restrict__ gid) {
    int n = blockIdx.x * blockDim.x + threadIdx.x;
    if (n < NN) atomicAdd(&g_cnt[gid[n]], 1.f);
}

// ---------------- SpMM kernels ----------------
// layer 0: agg[n, 0..19] = sum_{src in csr[n]} x[src] + esum[n]   (compact stride 20)
__global__ void k_spmm0(const float* __restrict__ x) {
    int warp = (blockIdx.x * blockDim.x + threadIdx.x) >> 5;
    int lane = threadIdx.x & 31;
    if (warp >= NN) return;
    int beg = g_rowptr[warp], end = g_rowptr[warp + 1];
    float s = 0.f;
    for (int j = beg; j < end; j++) {
        int sn = g_csrc[j];
        if (lane < DIN) s += x[sn * DIN + lane];
    }
    if (lane < DIN) g_agg[warp * DIN + lane] = s + g_esum[warp];
}

// layers 1..4: agg[n,f] = a[f]*sum_src h_raw[src,f] + deg*c[f] + esum[n]
__global__ void k_spmm300() {
    int n = blockIdx.x;
    int t = threadIdx.x;  // 128
    int beg = g_rowptr[n], end = g_rowptr[n + 1];
    float s0 = 0.f, s1 = 0.f, s2 = 0.f;
    for (int j = beg; j < end; j++) {
        const float* row = g_h + (size_t)g_csrc[j] * DEMB;
        s0 += row[t];
        s1 += row[t + 128];
        if (t < DEMB - 256) s2 += row[t + 256];
    }
    float es = g_esum[n];
    float dg = (float)(end - beg);
    float* o = g_agg + (size_t)n * DEMB;
    o[t]       = g_a[t] * s0       + dg * g_c[t]       + es;
    o[t + 128] = g_a[t + 128] * s1 + dg * g_c[t + 128] + es;
    if (t < DEMB - 256)
        o[t + 256] = g_a[t + 256] * s2 + dg * g_c[t + 256] + es;
}

// ---------------- SGEMM (C = A@B + bias, optional ReLU, optional col stats) ----------------
#define BM 128
#define BN 64
#define BK 16
#define TM 8
#define TN 4
#define APAD 4

template <bool RELU, bool STATS>
__global__ __launch_bounds__(256) void sgemm(
    const float* __restrict__ A, const float* __restrict__ B,
    const float* __restrict__ bias, float* __restrict__ C,
    int M, int N, int K, float* colsum, float* colsq) {
    __shared__ float As[BK][BM + APAD];
    __shared__ float Bs[BK][BN];
    int m0 = blockIdx.x * BM;
    int n0 = blockIdx.y * BN;
    int tid = threadIdx.x;
    int tx = tid & 15;   // col group (0..15), cols = tx*4..+3
    int ty = tid >> 4;   // row group (0..15), rows = ty*8..+7
    float acc[TM][TN] = {};

    for (int k0 = 0; k0 < K; k0 += BK) {
#pragma unroll
        for (int i = tid; i < BM * BK; i += 256) {
            int r = i / BK, c = i % BK;
            int gm = m0 + r, gk = k0 + c;
            As[c][r] = (gm < M && gk < K) ? A[(size_t)gm * K + gk] : 0.f;
        }
#pragma unroll
        for (int i = tid; i < BK * BN; i += 256) {
            int r = i / BN, c = i % BN;
            int gk = k0 + r, gn = n0 + c;
            Bs[r][c] = (gk < K && gn < N) ? B[(size_t)gk * N + gn] : 0.f;
        }
        __syncthreads();
#pragma unroll
        for (int kk = 0; kk < BK; kk++) {
            float ra[TM], rb[TN];
#pragma unroll
            for (int i = 0; i < TM; i++) ra[i] = As[kk][ty * TM + i];
#pragma unroll
            for (int j = 0; j < TN; j++) rb[j] = Bs[kk][tx * TN + j];
#pragma unroll
            for (int i = 0; i < TM; i++)
#pragma unroll
                for (int j = 0; j < TN; j++) acc[i][j] += ra[i] * rb[j];
        }
        __syncthreads();
    }

    float bsr[TN];
#pragma unroll
    for (int j = 0; j < TN; j++) {
        int gn = n0 + tx * TN + j;
        bsr[j] = (gn < N) ? bias[gn] : 0.f;
    }
    float csum[TN] = {}, csq[TN] = {};
#pragma unroll
    for (int i = 0; i < TM; i++) {
        int gm = m0 + ty * TM + i;
        if (gm >= M) continue;
#pragma unroll
        for (int j = 0; j < TN; j++) {
            int gn = n0 + tx * TN + j;
            if (gn >= N) continue;
            float v = acc[i][j] + bsr[j];
            if (RELU) v = fmaxf(v, 0.f);
            C[(size_t)gm * N + gn] = v;
            if (STATS) { csum[j] += v; csq[j] += v * v; }
        }
    }
    if (STATS) {
        __shared__ float s_sum[BN], s_sq[BN];
        if (tid < BN) { s_sum[tid] = 0.f; s_sq[tid] = 0.f; }
        __syncthreads();
#pragma unroll
        for (int j = 0; j < TN; j++) {
            atomicAdd(&s_sum[tx * TN + j], csum[j]);
            atomicAdd(&s_sq[tx * TN + j], csq[j]);
        }
        __syncthreads();
        if (tid < BN) {
            int gn = n0 + tid;
            if (gn < N) {
                atomicAdd(&colsum[gn], s_sum[tid]);
                atomicAdd(&colsq[gn], s_sq[tid]);
            }
        }
    }
}

// ---------------- BN finalize: a = gamma*rsqrt(var+eps); c = beta - mu*a ----------------
__global__ void k_bnfin(const float* __restrict__ gamma, const float* __restrict__ beta) {
    int f = threadIdx.x;
    if (f >= DEMB) return;
    const float invM = 1.0f / (float)NN;
    float mu = g_colsum[f] * invM;
    float var = g_colsq[f] * invM - mu * mu;
    float a = gamma[f] * rsqrtf(var + BN_EPS);
    g_a[f] = a;
    g_c[f] = beta[f] - mu * a;
}

// ---------------- pooling (graph_ids sorted -> block-local pre-reduction) ----------------
#define POOL_TILE 32
__global__ void k_pool(const int* __restrict__ gid) {
    int f = blockIdx.y * 128 + threadIdx.x;
    if (f >= DEMB) return;
    int n0 = blockIdx.x * POOL_TILE;
    float acc = 0.f;
    int cur = gid[n0];
    for (int i = 0; i < POOL_TILE; i++) {
        int n = n0 + i;
        int g = gid[n];
        if (g != cur) {
            atomicAdd(&g_pool[cur * DEMB + f], acc);
            acc = 0.f;
            cur = g;
        }
        acc += g_h[(size_t)n * DEMB + f];
    }
    atomicAdd(&g_pool[cur * DEMB + f], acc);
}

// ---------------- final: out[g,o] = ((a*pool + cnt*c)/max(cnt,1)) @ wt + bt ----------------
__global__ void k_final(const float* __restrict__ wt, const float* __restrict__ bt,
                        float* __restrict__ out) {
    int g = blockIdx.x;
    int o = threadIdx.x;  // 64
    float cnt = g_cnt[g];
    float inv = 1.0f / fmaxf(cnt, 1.f);
    float acc = 0.f;
    for (int f = 0; f < DEMB; f++) {
        float pf = (g_a[f] * g_pool[g * DEMB + f] + cnt * g_c[f]) * inv;
        acc += pf * wt[f * DOUT + o];
    }
    out[g * DOUT + o] = acc + bt[o];
}

// ---------------- host launcher ----------------
extern "C" void kernel_launch(void* const* d_in, const int* in_sizes, int n_in,
                              void* d_out, int out_size) {
    const float* node_feats = (const float*)d_in[0];
    const float* edge_feats = (const float*)d_in[1];
    const int*   src        = (const int*)d_in[2];
    const int*   dst        = (const int*)d_in[3];
    const int*   gid        = (const int*)d_in[4];
    const float* w1_0  = (const float*)d_in[5];
    const float* b1_0  = (const float*)d_in[6];
    const float* w2_0  = (const float*)d_in[7];
    const float* b2_0  = (const float*)d_in[8];
    const float* gamma0 = (const float*)d_in[9];
    const float* beta0  = (const float*)d_in[10];
    const float* w1   = (const float*)d_in[11];
    const float* b1   = (const float*)d_in[12];
    const float* w2   = (const float*)d_in[13];
    const float* b2   = (const float*)d_in[14];
    const float* gamma = (const float*)d_in[15];
    const float* beta  = (const float*)d_in[16];
    const float* wt   = (const float*)d_in[17];
    const float* bt   = (const float*)d_in[18];
    float* out = (float*)d_out;

    float *p_t, *p_h, *p_agg, *p_colsum, *p_colsq;
    cudaGetSymbolAddress((void**)&p_t, g_t);
    cudaGetSymbolAddress((void**)&p_h, g_h);
    cudaGetSymbolAddress((void**)&p_agg, g_agg);
    cudaGetSymbolAddress((void**)&p_colsum, g_colsum);
    cudaGetSymbolAddress((void**)&p_colsq, g_colsq);

    // ---- preprocessing (per call; captured in the graph) ----
    k_zero_pre<<<(NN + 255) / 256, 256>>>();
    k_zero_pool<<<(GG * DEMB + 255) / 256, 256>>>();
    k_edge_prep<<<(EE + 255) / 256, 256>>>(dst, edge_feats);
    k_scan<<<1, 1024>>>();
    k_edge_fill<<<(EE + 255) / 256, 256>>>(src, dst);
    k_counts<<<(NN + 255) / 256, 256>>>(gid);

    dim3 grid1((NN + BM - 1) / BM, (DHID + BN - 1) / BN);  // [N,600]
    dim3 grid2((NN + BM - 1) / BM, (DEMB + BN - 1) / BN);  // [N,300]

    // ---- layer 0 ----
    k_spmm0<<<(NN * 32 + 255) / 256, 256>>>(node_feats);
    k_zero_stats<<<1, 320>>>();
    sgemm<true, false><<<grid1, 256>>>(p_agg, w1_0, b1_0, p_t, NN, DHID, DIN, nullptr, nullptr);
    sgemm<false, true><<<grid2, 256>>>(p_t, w2_0, b2_0, p_h, NN, DEMB, DHID, p_colsum, p_colsq);
    k_bnfin<<<1, 320>>>(gamma0, beta0);

    // ---- layers 1..4 ----
    for (int l = 0; l < 4; l++) {
        k_spmm300<<<NN, 128>>>();
        k_zero_stats<<<1, 320>>>();
        sgemm<true, false><<<grid1, 256>>>(p_agg, w1 + (size_t)l * DEMB * DHID,
                                           b1 + (size_t)l * DHID, p_t, NN, DHID, DEMB,
                                           nullptr, nullptr);
        sgemm<false, true><<<grid2, 256>>>(p_t, w2 + (size_t)l * DHID * DEMB,
                                           b2 + (size_t)l * DEMB, p_h, NN, DEMB, DHID,
                                           p_colsum, p_colsq);
        k_bnfin<<<1, 320>>>(gamma + (size_t)l * DEMB, beta + (size_t)l * DEMB);
    }

    // ---- readout ----
    k_pool<<<dim3(NN / POOL_TILE, (DEMB + 127) / 128), 128>>>(gid);
    k_final<<<GG, DOUT>>>(wt, bt, out);
}

// round 3
// speedup vs baseline: 2.1509x; 2.1509x over previous
#include <cuda_runtime.h>
#include <cuda_bf16.h>
#include <math.h>
#include <stdint.h>

#define NN   100000
#define EE   1600000
#define GG   128
#define DEMB 300
#define DHID 600
#define DIN  20
#define DOUT 64
#define BN_EPS 1e-5f

// padded dims
#define KP1   320   // K for GEMM1 (layers 1..4): 300 -> 320
#define KP0   64    // K for GEMM1 layer 0: 20 -> 64
#define NP1   640   // N for GEMM1: 600 -> 640 (5 tiles of 128)
#define KP2   640   // K for GEMM2: 600 -> 640
#define NP2   384   // N for GEMM2: 300 -> 384 (3 tiles of 128)
#define HP    320   // h pitch (fp32)

// ---------------- scratch (device globals) ----------------
__device__ float         g_h[(size_t)NN * HP];
__device__ __nv_bfloat16 g_ahi[(size_t)NN * KP1];
__device__ __nv_bfloat16 g_alo[(size_t)NN * KP1];
__device__ __nv_bfloat16 g_thi[(size_t)NN * NP1];
__device__ __nv_bfloat16 g_tlo[(size_t)NN * NP1];
__device__ __nv_bfloat16 g_w1hi[NP1 * KP1];
__device__ __nv_bfloat16 g_w1lo[NP1 * KP1];
__device__ float         g_b1p[NP1];
__device__ __nv_bfloat16 g_w2hi[NP2 * KP2];
__device__ __nv_bfloat16 g_w2lo[NP2 * KP2];
__device__ float         g_b2p[NP2];

__device__ int   g_rowptr[NN + 1];
__device__ int   g_deg[NN];
__device__ int   g_cursor[NN];
__device__ int   g_csrc[EE];
__device__ float g_esum[NN];
__device__ float g_colsum[DEMB];
__device__ float g_colsq[DEMB];
__device__ float g_a[DEMB];
__device__ float g_c[DEMB];
__device__ float g_pool[GG * DEMB];
__device__ float g_cnt[GG];

// ---------------- PTX helpers (family-portable: cp.async / ldmatrix / mma.sync) ----------------
__device__ __forceinline__ uint32_t smem_u32(const void* p) {
    uint32_t a;
    asm("{ .reg .u64 t; cvta.to.shared.u64 t, %1; cvt.u32.u64 %0, t; }" : "=r"(a) : "l"(p));
    return a;
}
__device__ __forceinline__ void cp16(uint32_t d, const void* g, bool pred) {
    int sz = pred ? 16 : 0;
    asm volatile("cp.async.cg.shared.global [%0], [%1], 16, %2;"
                 :: "r"(d), "l"(g), "r"(sz) : "memory");
}
#define CP_COMMIT() asm volatile("cp.async.commit_group;" ::: "memory")
#define CP_WAIT1()  asm volatile("cp.async.wait_group 1;" ::: "memory")

__device__ __forceinline__ void ldsm_x4(uint32_t* r, uint32_t a) {
    asm volatile("ldmatrix.sync.aligned.m8n8.x4.shared.b16 {%0,%1,%2,%3}, [%4];"
                 : "=r"(r[0]), "=r"(r[1]), "=r"(r[2]), "=r"(r[3]) : "r"(a));
}
__device__ __forceinline__ void mma_bf16(float* c, const uint32_t* a, const uint32_t* b) {
    asm volatile(
        "mma.sync.aligned.m16n8k16.row.col.f32.bf16.bf16.f32 "
        "{%0,%1,%2,%3}, {%4,%5,%6,%7}, {%8,%9}, {%0,%1,%2,%3};"
        : "+f"(c[0]), "+f"(c[1]), "+f"(c[2]), "+f"(c[3])
        : "r"(a[0]), "r"(a[1]), "r"(a[2]), "r"(a[3]), "r"(b[0]), "r"(b[1]));
}
__device__ __forceinline__ uint32_t swz(uint32_t off) { return off ^ ((off >> 3) & 0x70); }

// ---------------- preprocessing kernels ----------------
__global__ void k_zero_pre() {
    int i = blockIdx.x * blockDim.x + threadIdx.x;
    if (i < NN) { g_deg[i] = 0; g_cursor[i] = 0; g_esum[i] = 0.f; }
}
__global__ void k_zero_pool() {
    int i = blockIdx.x * blockDim.x + threadIdx.x;
    if (i < GG * DEMB) g_pool[i] = 0.f;
    if (i < GG) g_cnt[i] = 0.f;
}
__global__ void k_zero_stats() {
    int i = threadIdx.x;
    if (i < DEMB) { g_colsum[i] = 0.f; g_colsq[i] = 0.f; }
}
__global__ void k_edge_prep(const int* __restrict__ dst, const float* __restrict__ ef) {
    int e = blockIdx.x * blockDim.x + threadIdx.x;
    if (e < EE) {
        int d = dst[e];
        atomicAdd(&g_deg[d], 1);
        atomicAdd(&g_esum[d], ef[e]);
    }
}
__global__ void k_scan() {
    __shared__ int sh[1024];
    __shared__ int carry;
    if (threadIdx.x == 0) carry = 0;
    __syncthreads();
    for (int base = 0; base < NN; base += 1024) {
        int i = base + threadIdx.x;
        int v = (i < NN) ? g_deg[i] : 0;
        sh[threadIdx.x] = v;
        __syncthreads();
        for (int off = 1; off < 1024; off <<= 1) {
            int t = (threadIdx.x >= off) ? sh[threadIdx.x - off] : 0;
            __syncthreads();
            sh[threadIdx.x] += t;
            __syncthreads();
        }
        if (i < NN) g_rowptr[i] = carry + sh[threadIdx.x] - v;
        __syncthreads();
        if (threadIdx.x == 0) carry += sh[1023];
        __syncthreads();
    }
    if (threadIdx.x == 0) g_rowptr[NN] = carry;
}
__global__ void k_edge_fill(const int* __restrict__ src, const int* __restrict__ dst) {
    int e = blockIdx.x * blockDim.x + threadIdx.x;
    if (e < EE) {
        int d = dst[e];
        int pos = atomicAdd(&g_cursor[d], 1);
        g_csrc[g_rowptr[d] + pos] = src[e];
    }
}
__global__ void k_counts(const int* __restrict__ gid) {
    int n = blockIdx.x * blockDim.x + threadIdx.x;
    if (n < NN) atomicAdd(&g_cnt[gid[n]], 1.f);
}

// ---------------- weight prep: transpose + pad + bf16 split ----------------
__global__ void k_prepw(const float* __restrict__ w, const float* __restrict__ bias,
                        int K, int Nn, int KPp, int NPp,
                        __nv_bfloat16* __restrict__ whiT, __nv_bfloat16* __restrict__ wloT,
                        float* __restrict__ bp) {
    int idx = blockIdx.x * blockDim.x + threadIdx.x;
    if (idx >= NPp * KPp) return;
    int nrow = idx / KPp, k = idx - nrow * KPp;
    float v = (nrow < Nn && k < K) ? w[(size_t)k * Nn + nrow] : 0.f;
    __nv_bfloat16 hi = __float2bfloat16(v);
    float lo = v - __bfloat162float(hi);
    whiT[idx] = hi;
    wloT[idx] = __float2bfloat16(lo);
    if (k == 0) bp[nrow] = (nrow < Nn) ? bias[nrow] : 0.f;
}

// ---------------- SpMM kernels (emit bf16 hi/lo) ----------------
__global__ void k_spmm0(const float* __restrict__ x) {
    int warp = (blockIdx.x * blockDim.x + threadIdx.x) >> 5;
    int lane = threadIdx.x & 31;
    if (warp >= NN) return;
    int beg = g_rowptr[warp], end = g_rowptr[warp + 1];
    float s = 0.f;
    for (int j = beg; j < end; j++) {
        int sn = g_csrc[j];
        if (lane < DIN) s += x[sn * DIN + lane];
    }
    float v0 = (lane < DIN) ? (s + g_esum[warp]) : 0.f;
    size_t o = (size_t)warp * KP0;
    __nv_bfloat16 hi = __float2bfloat16(v0);
    g_ahi[o + lane] = hi;
    g_alo[o + lane] = __float2bfloat16(v0 - __bfloat162float(hi));
    g_ahi[o + lane + 32] = __float2bfloat16(0.f);
    g_alo[o + lane + 32] = __float2bfloat16(0.f);
}

__global__ void k_spmm300() {
    int n = blockIdx.x;
    int t = threadIdx.x;  // 128
    int beg = g_rowptr[n], end = g_rowptr[n + 1];
    float s0 = 0.f, s1 = 0.f, s2 = 0.f;
    for (int j = beg; j < end; j++) {
        const float* row = g_h + (size_t)g_csrc[j] * HP;
        s0 += row[t];
        s1 += row[t + 128];
        if (t < DEMB - 256) s2 += row[t + 256];
    }
    float es = g_esum[n];
    float dg = (float)(end - beg);
    size_t o = (size_t)n * KP1;
    float v0 = g_a[t] * s0 + dg * g_c[t] + es;
    float v1 = g_a[t + 128] * s1 + dg * g_c[t + 128] + es;
    __nv_bfloat16 h0 = __float2bfloat16(v0);
    __nv_bfloat16 h1 = __float2bfloat16(v1);
    g_ahi[o + t] = h0;       g_alo[o + t]       = __float2bfloat16(v0 - __bfloat162float(h0));
    g_ahi[o + t + 128] = h1; g_alo[o + t + 128] = __float2bfloat16(v1 - __bfloat162float(h1));
    if (t + 256 < KP1) {
        float v2 = (t + 256 < DEMB) ? (g_a[t + 256] * s2 + dg * g_c[t + 256] + es) : 0.f;
        __nv_bfloat16 h2 = __float2bfloat16(v2);
        g_ahi[o + t + 256] = h2;
        g_alo[o + t + 256] = __float2bfloat16(v2 - __bfloat162float(h2));
    }
}

// ---------------- mma.sync bf16 GEMM (3-term split, fp32 acc) ----------------
// C[M,N] = (Ahi+Alo)[M,K] x (Bhi+Blo)[N,K]^T
// MODE 0: bias + ReLU -> Ohi/Olo bf16 (pitch NP1)
// MODE 1: bias -> H fp32 (pitch HP, cols<HP) + column stats (cols<DEMB)
#define BM 128
#define BN 128
#define BK 64
#define GSTAGE  65536
#define OFF_AHI 0
#define OFF_ALO 16384
#define OFF_BHI 32768
#define OFF_BLO 49152
#define GSMEM   (3 * GSTAGE + 1024)

template <int MODE>
__global__ __launch_bounds__(256, 1) void k_gemm(
    const __nv_bfloat16* __restrict__ Ahi, const __nv_bfloat16* __restrict__ Alo, int KP,
    const __nv_bfloat16* __restrict__ Bhi, const __nv_bfloat16* __restrict__ Blo,
    const float* __restrict__ biasp, int nk,
    __nv_bfloat16* __restrict__ Ohi, __nv_bfloat16* __restrict__ Olo,
    float* __restrict__ H, float* __restrict__ colsum, float* __restrict__ colsq) {
    extern __shared__ char dyn[];
    __shared__ float s_bias[BN];
    __shared__ float s_sum[BN], s_sq[BN];

    int tid = threadIdx.x;
    int wid = tid >> 5;
    int lane = tid & 31;
    int wm = wid >> 2;   // 0..1  (m offset wm*64)
    int wn = wid & 3;    // 0..3  (n offset wn*32)
    int m0 = blockIdx.x * BM;
    int n0 = blockIdx.y * BN;

    uint32_t dynb0 = smem_u32(dyn);
    uint32_t dynb = (dynb0 + 1023u) & ~1023u;

    if (tid < BN) {
        s_bias[tid] = biasp[n0 + tid];
        if (MODE == 1) { s_sum[tid] = 0.f; s_sq[tid] = 0.f; }
    }

    float acc[4][4][4] = {};

    auto load_stage = [&](int s, int kt) {
        uint32_t ab = dynb + s * GSTAGE;
        int k0 = kt * BK;
#pragma unroll
        for (int it = 0; it < 8; it++) {
            int i = tid + it * 256;
            int var = i >> 10;
            int j = i & 1023;
            int r = j >> 3, sg = j & 7;
            const __nv_bfloat16* base = var ? Alo : Ahi;
            const void* g = base + (size_t)(m0 + r) * KP + k0 + sg * 8;
            uint32_t d = ab + (var ? OFF_ALO : OFF_AHI) + swz((uint32_t)(r * 128 + sg * 16));
            cp16(d, g, (m0 + r) < NN);
        }
#pragma unroll
        for (int it = 0; it < 8; it++) {
            int i = tid + it * 256;
            int var = i >> 10;
            int j = i & 1023;
            int r = j >> 3, sg = j & 7;
            const __nv_bfloat16* base = var ? Blo : Bhi;
            const void* g = base + (size_t)(n0 + r) * KP + k0 + sg * 8;
            uint32_t d = ab + (var ? OFF_BLO : OFF_BHI) + swz((uint32_t)(r * 128 + sg * 16));
            cp16(d, g, true);
        }
    };

    int lr = (lane & 7) + ((lane >> 3) & 1) * 8;   // ldmatrix row within 16
    int lc = ((lane >> 4) & 1) * 16;               // ldmatrix 16B col (k8..15)

    auto compute = [&](int s) {
        uint32_t ab = dynb + s * GSTAGE;
#pragma unroll
        for (int ks = 0; ks < 4; ks++) {
            int kb = ks * 32;
            uint32_t ah[4][4], al[4][4];
#pragma unroll
            for (int mi = 0; mi < 4; mi++) {
                uint32_t off = swz((uint32_t)((wm * 64 + mi * 16 + lr) * 128 + kb + lc));
                ldsm_x4(ah[mi], ab + OFF_AHI + off);
                ldsm_x4(al[mi], ab + OFF_ALO + off);
            }
            uint32_t bh[2][4], bl[2][4];
#pragma unroll
            for (int bi = 0; bi < 2; bi++) {
                uint32_t off = swz((uint32_t)((wn * 32 + bi * 16 + lr) * 128 + kb + lc));
                ldsm_x4(bh[bi], ab + OFF_BHI + off);
                ldsm_x4(bl[bi], ab + OFF_BLO + off);
            }
#pragma unroll
            for (int mi = 0; mi < 4; mi++) {
#pragma unroll
                for (int t = 0; t < 4; t++) {
                    uint32_t bfh[2] = { bh[t >> 1][t & 1], bh[t >> 1][(t & 1) + 2] };
                    uint32_t bfl[2] = { bl[t >> 1][t & 1], bl[t >> 1][(t & 1) + 2] };
                    mma_bf16(acc[mi][t], ah[mi], bfh);
                    mma_bf16(acc[mi][t], al[mi], bfh);
                    mma_bf16(acc[mi][t], ah[mi], bfl);
                }
            }
        }
    };

    // 3-stage cp.async pipeline
    load_stage(0, 0);
    CP_COMMIT();
    if (nk > 1) load_stage(1, 1);
    CP_COMMIT();
    for (int kt = 0; kt < nk; kt++) {
        CP_WAIT1();
        __syncthreads();
        if (kt + 2 < nk) load_stage((kt + 2) % 3, kt + 2);
        CP_COMMIT();
        compute(kt % 3);
    }

    // ---------------- epilogue ----------------
    int lrow = lane >> 2;
    int lcol = (lane & 3) * 2;

    if (MODE == 0) {
#pragma unroll
        for (int mi = 0; mi < 4; mi++) {
            int gm = m0 + wm * 64 + mi * 16 + lrow;
#pragma unroll
            for (int t = 0; t < 4; t++) {
                int c = wn * 32 + t * 8 + lcol;
                float b0 = s_bias[c], b1 = s_bias[c + 1];
                int cg = n0 + c;
#pragma unroll
                for (int rr = 0; rr < 2; rr++) {
                    int g = gm + rr * 8;
                    if (g < NN) {
                        float v0 = fmaxf(acc[mi][t][rr * 2 + 0] + b0, 0.f);
                        float v1 = fmaxf(acc[mi][t][rr * 2 + 1] + b1, 0.f);
                        __nv_bfloat16 h0 = __float2bfloat16(v0), h1 = __float2bfloat16(v1);
                        float r0 = v0 - __bfloat162float(h0);
                        float r1 = v1 - __bfloat162float(h1);
                        __nv_bfloat16 l0 = __float2bfloat16(r0), l1 = __float2bfloat16(r1);
                        uint32_t hp = (uint32_t)__bfloat16_as_ushort(h0) |
                                      ((uint32_t)__bfloat16_as_ushort(h1) << 16);
                        uint32_t lp = (uint32_t)__bfloat16_as_ushort(l0) |
                                      ((uint32_t)__bfloat16_as_ushort(l1) << 16);
                        *(uint32_t*)(Ohi + (size_t)g * NP1 + cg) = hp;
                        *(uint32_t*)(Olo + (size_t)g * NP1 + cg) = lp;
                    }
                }
            }
        }
    } else {
#pragma unroll
        for (int t = 0; t < 4; t++) {
            int c = wn * 32 + t * 8 + lcol;
            int cg = n0 + c;
            float b0 = s_bias[c], b1 = s_bias[c + 1];
            float s0 = 0.f, s1 = 0.f, q0 = 0.f, q1 = 0.f;
#pragma unroll
            for (int mi = 0; mi < 4; mi++) {
                int gm = m0 + wm * 64 + mi * 16 + lrow;
                float v0 = acc[mi][t][0] + b0, v1 = acc[mi][t][1] + b1;
                float v2 = acc[mi][t][2] + b0, v3 = acc[mi][t][3] + b1;
                if (gm >= NN) { v0 = 0.f; v1 = 0.f; }
                if (gm + 8 >= NN) { v2 = 0.f; v3 = 0.f; }
                if (cg < HP) {
                    if (gm < NN) *(float2*)(H + (size_t)gm * HP + cg) = make_float2(v0, v1);
                    if (gm + 8 < NN) *(float2*)(H + (size_t)(gm + 8) * HP + cg) = make_float2(v2, v3);
                }
                s0 += v0 + v2; s1 += v1 + v3;
                q0 += v0 * v0 + v2 * v2; q1 += v1 * v1 + v3 * v3;
            }
#pragma unroll
            for (int off = 4; off < 32; off <<= 1) {
                s0 += __shfl_xor_sync(0xffffffffu, s0, off);
                s1 += __shfl_xor_sync(0xffffffffu, s1, off);
                q0 += __shfl_xor_sync(0xffffffffu, q0, off);
                q1 += __shfl_xor_sync(0xffffffffu, q1, off);
            }
            if (lane < 4) {
                if (cg < DEMB) { atomicAdd(&s_sum[c], s0); atomicAdd(&s_sq[c], q0); }
                if (cg + 1 < DEMB) { atomicAdd(&s_sum[c + 1], s1); atomicAdd(&s_sq[c + 1], q1); }
            }
        }
        __syncthreads();
        if (tid < BN) {
            int n = n0 + tid;
            if (n < DEMB) {
                atomicAdd(&colsum[n], s_sum[tid]);
                atomicAdd(&colsq[n], s_sq[tid]);
            }
        }
    }
}

// ---------------- BN finalize ----------------
__global__ void k_bnfin(const float* __restrict__ gamma, const float* __restrict__ beta) {
    int f = threadIdx.x;
    if (f >= DEMB) return;
    const float invM = 1.0f / (float)NN;
    float mu = g_colsum[f] * invM;
    float var = g_colsq[f] * invM - mu * mu;
    float a = gamma[f] * rsqrtf(var + BN_EPS);
    g_a[f] = a;
    g_c[f] = beta[f] - mu * a;
}

// ---------------- pooling ----------------
#define POOL_TILE 32
__global__ void k_pool(const int* __restrict__ gid) {
    int f = blockIdx.y * 128 + threadIdx.x;
    if (f >= DEMB) return;
    int n0 = blockIdx.x * POOL_TILE;
    float acc = 0.f;
    int cur = gid[n0];
    for (int i = 0; i < POOL_TILE; i++) {
        int n = n0 + i;
        int g = gid[n];
        if (g != cur) {
            atomicAdd(&g_pool[cur * DEMB + f], acc);
            acc = 0.f;
            cur = g;
        }
        acc += g_h[(size_t)n * HP + f];
    }
    atomicAdd(&g_pool[cur * DEMB + f], acc);
}

// ---------------- final ----------------
__global__ void k_final(const float* __restrict__ wt, const float* __restrict__ bt,
                        float* __restrict__ out) {
    int g = blockIdx.x;
    int o = threadIdx.x;
    float cnt = g_cnt[g];
    float inv = 1.0f / fmaxf(cnt, 1.f);
    float acc = 0.f;
    for (int f = 0; f < DEMB; f++) {
        float pf = (g_a[f] * g_pool[g * DEMB + f] + cnt * g_c[f]) * inv;
        acc += pf * wt[f * DOUT + o];
    }
    out[g * DOUT + o] = acc + bt[o];
}

// ---------------- host launcher ----------------
extern "C" void kernel_launch(void* const* d_in, const int* in_sizes, int n_in,
                              void* d_out, int out_size) {
    const float* node_feats = (const float*)d_in[0];
    const float* edge_feats = (const float*)d_in[1];
    const int*   src        = (const int*)d_in[2];
    const int*   dst        = (const int*)d_in[3];
    const int*   gid        = (const int*)d_in[4];
    const float* w1_0  = (const float*)d_in[5];
    const float* b1_0  = (const float*)d_in[6];
    const float* w2_0  = (const float*)d_in[7];
    const float* b2_0  = (const float*)d_in[8];
    const float* gamma0 = (const float*)d_in[9];
    const float* beta0  = (const float*)d_in[10];
    const float* w1   = (const float*)d_in[11];
    const float* b1   = (const float*)d_in[12];
    const float* w2   = (const float*)d_in[13];
    const float* b2   = (const float*)d_in[14];
    const float* gamma = (const float*)d_in[15];
    const float* beta  = (const float*)d_in[16];
    const float* wt   = (const float*)d_in[17];
    const float* bt   = (const float*)d_in[18];
    float* out = (float*)d_out;

    static bool attr_done = false;
    if (!attr_done) {
        cudaFuncSetAttribute(k_gemm<0>, cudaFuncAttributeMaxDynamicSharedMemorySize, GSMEM);
        cudaFuncSetAttribute(k_gemm<1>, cudaFuncAttributeMaxDynamicSharedMemorySize, GSMEM);
        attr_done = true;
    }

    __nv_bfloat16 *p_ahi, *p_alo, *p_thi, *p_tlo, *p_w1hi, *p_w1lo, *p_w2hi, *p_w2lo;
    float *p_h, *p_b1p, *p_b2p, *p_colsum, *p_colsq;
    cudaGetSymbolAddress((void**)&p_ahi, g_ahi);
    cudaGetSymbolAddress((void**)&p_alo, g_alo);
    cudaGetSymbolAddress((void**)&p_thi, g_thi);
    cudaGetSymbolAddress((void**)&p_tlo, g_tlo);
    cudaGetSymbolAddress((void**)&p_w1hi, g_w1hi);
    cudaGetSymbolAddress((void**)&p_w1lo, g_w1lo);
    cudaGetSymbolAddress((void**)&p_w2hi, g_w2hi);
    cudaGetSymbolAddress((void**)&p_w2lo, g_w2lo);
    cudaGetSymbolAddress((void**)&p_h, g_h);
    cudaGetSymbolAddress((void**)&p_b1p, g_b1p);
    cudaGetSymbolAddress((void**)&p_b2p, g_b2p);
    cudaGetSymbolAddress((void**)&p_colsum, g_colsum);
    cudaGetSymbolAddress((void**)&p_colsq, g_colsq);

    // ---- preprocessing ----
    k_zero_pre<<<(NN + 255) / 256, 256>>>();
    k_zero_pool<<<(GG * DEMB + 255) / 256, 256>>>();
    k_edge_prep<<<(EE + 255) / 256, 256>>>(dst, edge_feats);
    k_scan<<<1, 1024>>>();
    k_edge_fill<<<(EE + 255) / 256, 256>>>(src, dst);
    k_counts<<<(NN + 255) / 256, 256>>>(gid);

    const int MT = (NN + BM - 1) / BM;       // 782
    dim3 grid1(MT, NP1 / BN);                // (782, 5)
    dim3 grid2(MT, NP2 / BN);                // (782, 3)

    // ---- layer 0 ----
    k_prepw<<<(NP1 * KP0 + 255) / 256, 256>>>(w1_0, b1_0, DIN, DHID, KP0, NP1,
                                              p_w1hi, p_w1lo, p_b1p);
    k_prepw<<<(NP2 * KP2 + 255) / 256, 256>>>(w2_0, b2_0, DHID, DEMB, KP2, NP2,
                                              p_w2hi, p_w2lo, p_b2p);
    k_spmm0<<<(NN * 32 + 255) / 256, 256>>>(node_feats);
    k_zero_stats<<<1, 320>>>();
    k_gemm<0><<<grid1, 256, GSMEM>>>(p_ahi, p_alo, KP0, p_w1hi, p_w1lo, p_b1p,
                                     KP0 / BK, p_thi, p_tlo, nullptr, nullptr, nullptr);
    k_gemm<1><<<grid2, 256, GSMEM>>>(p_thi, p_tlo, KP2, p_w2hi, p_w2lo, p_b2p,
                                     KP2 / BK, nullptr, nullptr, p_h, p_colsum, p_colsq);
    k_bnfin<<<1, 320>>>(gamma0, beta0);

    // ---- layers 1..4 ----
    for (int l = 0; l < 4; l++) {
        k_prepw<<<(NP1 * KP1 + 255) / 256, 256>>>(w1 + (size_t)l * DEMB * DHID,
                                                  b1 + (size_t)l * DHID, DEMB, DHID, KP1, NP1,
                                                  p_w1hi, p_w1lo, p_b1p);
        k_prepw<<<(NP2 * KP2 + 255) / 256, 256>>>(w2 + (size_t)l * DHID * DEMB,
                                                  b2 + (size_t)l * DEMB, DHID, DEMB, KP2, NP2,
                                                  p_w2hi, p_w2lo, p_b2p);
        k_spmm300<<<NN, 128>>>();
        k_zero_stats<<<1, 320>>>();
        k_gemm<0><<<grid1, 256, GSMEM>>>(p_ahi, p_alo, KP1, p_w1hi, p_w1lo, p_b1p,
                                         KP1 / BK, p_thi, p_tlo, nullptr, nullptr, nullptr);
        k_gemm<1><<<grid2, 256, GSMEM>>>(p_thi, p_tlo, KP2, p_w2hi, p_w2lo, p_b2p,
                                         KP2 / BK, nullptr, nullptr, p_h, p_colsum, p_colsq);
        k_bnfin<<<1, 320>>>(gamma + (size_t)l * DEMB, beta + (size_t)l * DEMB);
    }

    // ---- readout ----
    k_pool<<<dim3(NN / POOL_TILE, (DEMB + 127) / 128), 128>>>(gid);
    k_final<<<GG, DOUT>>>(wt, bt, out);
}

// round 4
// speedup vs baseline: 2.2913x; 1.0653x over previous
#include <cuda_runtime.h>
#include <cuda_bf16.h>
#include <math.h>
#include <stdint.h>

#define NN   100000
#define EE   1600000
#define GG   128
#define DEMB 300
#define DHID 600
#define DIN  20
#define DOUT 64
#define BN_EPS 1e-5f

// padded dims
#define KP1   320
#define KP0   64
#define NP1   640   // GEMM1 N: 600 -> 640 (5 tiles of 128)
#define KP2   640
#define NP2   320   // GEMM2 N: 300 -> 320 (2x128 + 1x64)
#define HP    320

// ---------------- scratch (device globals) ----------------
__device__ float         g_h[(size_t)NN * HP];
__device__ __nv_bfloat16 g_ahi[(size_t)NN * KP1];
__device__ __nv_bfloat16 g_alo[(size_t)NN * KP1];
__device__ __nv_bfloat16 g_thi[(size_t)NN * NP1];
__device__ __nv_bfloat16 g_tlo[(size_t)NN * NP1];
__device__ __nv_bfloat16 g_w1hi[NP1 * KP1];
__device__ __nv_bfloat16 g_w1lo[NP1 * KP1];
__device__ float         g_b1p[NP1];
__device__ __nv_bfloat16 g_w2hi[NP2 * KP2];
__device__ __nv_bfloat16 g_w2lo[NP2 * KP2];
__device__ float         g_b2p[NP2];

__device__ int   g_rowptr[NN + 1];
__device__ int   g_deg[NN];
__device__ int   g_cursor[NN];
__device__ int   g_csrc[EE];
__device__ float g_esum[NN];
__device__ int   g_blksum[128];
__device__ int   g_blkoff[128];
__device__ float g_colsum[DEMB];
__device__ float g_colsq[DEMB];
__device__ float g_a[DEMB];
__device__ float g_c[DEMB];
__device__ float g_pool[GG * DEMB];
__device__ float g_cnt[GG];

#define SCAN_NB ((NN + 1023) / 1024)   // 98

// ---------------- PTX helpers ----------------
__device__ __forceinline__ uint32_t smem_u32(const void* p) {
    uint32_t a;
    asm("{ .reg .u64 t; cvta.to.shared.u64 t, %1; cvt.u32.u64 %0, t; }" : "=r"(a) : "l"(p));
    return a;
}
__device__ __forceinline__ void cp16(uint32_t d, const void* g, bool pred) {
    int sz = pred ? 16 : 0;
    asm volatile("cp.async.cg.shared.global [%0], [%1], 16, %2;"
                 :: "r"(d), "l"(g), "r"(sz) : "memory");
}
#define CP_COMMIT() asm volatile("cp.async.commit_group;" ::: "memory")
#define CP_WAIT1()  asm volatile("cp.async.wait_group 1;" ::: "memory")

__device__ __forceinline__ void ldsm_x4(uint32_t* r, uint32_t a) {
    asm volatile("ldmatrix.sync.aligned.m8n8.x4.shared.b16 {%0,%1,%2,%3}, [%4];"
                 : "=r"(r[0]), "=r"(r[1]), "=r"(r[2]), "=r"(r[3]) : "r"(a));
}
__device__ __forceinline__ void mma_bf16(float* c, const uint32_t* a, const uint32_t* b) {
    asm volatile(
        "mma.sync.aligned.m16n8k16.row.col.f32.bf16.bf16.f32 "
        "{%0,%1,%2,%3}, {%4,%5,%6,%7}, {%8,%9}, {%0,%1,%2,%3};"
        : "+f"(c[0]), "+f"(c[1]), "+f"(c[2]), "+f"(c[3])
        : "r"(a[0]), "r"(a[1]), "r"(a[2]), "r"(a[3]), "r"(b[0]), "r"(b[1]));
}
__device__ __forceinline__ uint32_t swz(uint32_t off) { return off ^ ((off >> 3) & 0x70); }

// ---------------- preprocessing kernels ----------------
__global__ void k_zero_pre() {
    int i = blockIdx.x * blockDim.x + threadIdx.x;
    if (i < NN) { g_deg[i] = 0; g_cursor[i] = 0; g_esum[i] = 0.f; }
}
__global__ void k_zero_pool() {
    int i = blockIdx.x * blockDim.x + threadIdx.x;
    if (i < GG * DEMB) g_pool[i] = 0.f;
    if (i < GG) g_cnt[i] = 0.f;
}
__global__ void k_zero_stats() {
    int i = threadIdx.x;
    if (i < DEMB) { g_colsum[i] = 0.f; g_colsq[i] = 0.f; }
}
__global__ void k_edge_prep(const int* __restrict__ dst, const float* __restrict__ ef) {
    int e = blockIdx.x * blockDim.x + threadIdx.x;
    if (e < EE) {
        int d = dst[e];
        atomicAdd(&g_deg[d], 1);
        atomicAdd(&g_esum[d], ef[e]);
    }
}
// parallel scan: block-local inclusive scan -> blksum; then scan blksums; then add
__global__ void k_scan1() {
    __shared__ int sh[1024];
    int b = blockIdx.x;
    int i = b * 1024 + threadIdx.x;
    int v = (i < NN) ? g_deg[i] : 0;
    sh[threadIdx.x] = v;
    __syncthreads();
#pragma unroll
    for (int off = 1; off < 1024; off <<= 1) {
        int t = (threadIdx.x >= off) ? sh[threadIdx.x - off] : 0;
        __syncthreads();
        sh[threadIdx.x] += t;
        __syncthreads();
    }
    if (i < NN) g_rowptr[i] = sh[threadIdx.x] - v;  // block-local exclusive
    if (threadIdx.x == 1023) g_blksum[b] = sh[1023];
}
__global__ void k_scan2() {
    __shared__ int sh[128];
    int t = threadIdx.x;
    int v = (t < SCAN_NB) ? g_blksum[t] : 0;
    sh[t] = v;
    __syncthreads();
#pragma unroll
    for (int off = 1; off < 128; off <<= 1) {
        int x = (t >= off) ? sh[t - off] : 0;
        __syncthreads();
        sh[t] += x;
        __syncthreads();
    }
    if (t < SCAN_NB) g_blkoff[t] = sh[t] - v;  // exclusive
    if (t == 0) g_rowptr[NN] = EE;
}
__global__ void k_scan3() {
    int b = blockIdx.x;
    int i = b * 1024 + threadIdx.x;
    if (i < NN) g_rowptr[i] += g_blkoff[b];
}
__global__ void k_edge_fill(const int* __restrict__ src, const int* __restrict__ dst) {
    int e = blockIdx.x * blockDim.x + threadIdx.x;
    if (e < EE) {
        int d = dst[e];
        int pos = atomicAdd(&g_cursor[d], 1);
        g_csrc[g_rowptr[d] + pos] = src[e];
    }
}
__global__ void k_counts(const int* __restrict__ gid) {
    int n = blockIdx.x * blockDim.x + threadIdx.x;
    if (n < NN) atomicAdd(&g_cnt[gid[n]], 1.f);
}

// ---------------- weight prep: transpose + pad + bf16 split ----------------
__global__ void k_prepw(const float* __restrict__ w, const float* __restrict__ bias,
                        int K, int Nn, int KPp, int NPp,
                        __nv_bfloat16* __restrict__ whiT, __nv_bfloat16* __restrict__ wloT,
                        float* __restrict__ bp) {
    int idx = blockIdx.x * blockDim.x + threadIdx.x;
    if (idx >= NPp * KPp) return;
    int nrow = idx / KPp, k = idx - nrow * KPp;
    float v = (nrow < Nn && k < K) ? w[(size_t)k * Nn + nrow] : 0.f;
    __nv_bfloat16 hi = __float2bfloat16(v);
    float lo = v - __bfloat162float(hi);
    whiT[idx] = hi;
    wloT[idx] = __float2bfloat16(lo);
    if (k == 0) bp[nrow] = (nrow < Nn) ? bias[nrow] : 0.f;
}

// ---------------- SpMM kernels (emit bf16 hi/lo) ----------------
__global__ void k_spmm0(const float* __restrict__ x) {
    int warp = (blockIdx.x * blockDim.x + threadIdx.x) >> 5;
    int lane = threadIdx.x & 31;
    if (warp >= NN) return;
    int beg = g_rowptr[warp], end = g_rowptr[warp + 1];
    float s = 0.f;
    for (int j = beg; j < end; j++) {
        int sn = g_csrc[j];
        if (lane < DIN) s += x[sn * DIN + lane];
    }
    float v0 = (lane < DIN) ? (s + g_esum[warp]) : 0.f;
    size_t o = (size_t)warp * KP0;
    __nv_bfloat16 hi = __float2bfloat16(v0);
    g_ahi[o + lane] = hi;
    g_alo[o + lane] = __float2bfloat16(v0 - __bfloat162float(hi));
    g_ahi[o + lane + 32] = __float2bfloat16(0.f);
    g_alo[o + lane + 32] = __float2bfloat16(0.f);
}

__global__ void k_spmm300() {
    int n = blockIdx.x;
    int t = threadIdx.x;  // 128
    int beg = g_rowptr[n], end = g_rowptr[n + 1];
    float s0 = 0.f, s1 = 0.f, s2 = 0.f;
    for (int j = beg; j < end; j++) {
        const float* row = g_h + (size_t)g_csrc[j] * HP;
        s0 += row[t];
        s1 += row[t + 128];
        if (t < DEMB - 256) s2 += row[t + 256];
    }
    float es = g_esum[n];
    float dg = (float)(end - beg);
    size_t o = (size_t)n * KP1;
    float v0 = g_a[t] * s0 + dg * g_c[t] + es;
    float v1 = g_a[t + 128] * s1 + dg * g_c[t + 128] + es;
    __nv_bfloat16 h0 = __float2bfloat16(v0);
    __nv_bfloat16 h1 = __float2bfloat16(v1);
    g_ahi[o + t] = h0;       g_alo[o + t]       = __float2bfloat16(v0 - __bfloat162float(h0));
    g_ahi[o + t + 128] = h1; g_alo[o + t + 128] = __float2bfloat16(v1 - __bfloat162float(h1));
    if (t + 256 < KP1) {
        float v2 = (t + 256 < DEMB) ? (g_a[t + 256] * s2 + dg * g_c[t + 256] + es) : 0.f;
        __nv_bfloat16 h2 = __float2bfloat16(v2);
        g_ahi[o + t + 256] = h2;
        g_alo[o + t + 256] = __float2bfloat16(v2 - __bfloat162float(h2));
    }
}

// ---------------- mma.sync bf16 GEMM (3-term split, fp32 acc), 512 threads ----------------
// MODE 0: bias + ReLU -> Ohi/Olo bf16 (pitch NP1)
// MODE 1: bias -> H fp32 (cols<HP) + column stats (cols<DEMB)
#define BM 128
#define BK 64

template <int MODE, int BNT>
__global__ __launch_bounds__(512, 1) void k_gemm(
    const __nv_bfloat16* __restrict__ Ahi, const __nv_bfloat16* __restrict__ Alo, int KP,
    const __nv_bfloat16* __restrict__ Bhi, const __nv_bfloat16* __restrict__ Blo,
    const float* __restrict__ biasp, int nk, int n0_base,
    __nv_bfloat16* __restrict__ Ohi, __nv_bfloat16* __restrict__ Olo,
    float* __restrict__ H, float* __restrict__ colsum, float* __restrict__ colsq) {
    constexpr int WN_W = BNT / 32;        // warps along n
    constexpr int WM_W = 16 / WN_W;       // warps along m
    constexpr int MT_W = BM / WM_W;       // rows per warp
    constexpr int MI   = MT_W / 16;       // 16-row chunks per warp
    constexpr int OFF_ALO_ = 16384;
    constexpr int OFF_BHI_ = 32768;
    constexpr int OFF_BLO_ = 32768 + BNT * 128;
    constexpr int STAGE_   = 32768 + 2 * BNT * 128;

    extern __shared__ char dyn[];
    __shared__ float s_bias[128];
    __shared__ float s_sum[128], s_sq[128];

    int tid = threadIdx.x;
    int wid = tid >> 5;
    int lane = tid & 31;
    int wm = wid / WN_W;
    int wn = wid % WN_W;
    int m0 = blockIdx.x * BM;
    int n0 = n0_base + blockIdx.y * BNT;

    uint32_t dynb0 = smem_u32(dyn);
    uint32_t dynb = (dynb0 + 1023u) & ~1023u;

    if (tid < BNT) {
        s_bias[tid] = biasp[n0 + tid];
        if (MODE == 1) { s_sum[tid] = 0.f; s_sq[tid] = 0.f; }
    }

    float acc[MI][4][4] = {};

    auto load_stage = [&](int s, int kt) {
        uint32_t ab = dynb + s * STAGE_;
        int k0 = kt * BK;
#pragma unroll
        for (int it = 0; it < 4; it++) {            // A: 2048 cp16 / 512 thr
            int i = tid + it * 512;
            int var = i >> 10;
            int j = i & 1023;
            int r = j >> 3, sg = j & 7;
            const __nv_bfloat16* base = var ? Alo : Ahi;
            const void* g = base + (size_t)(m0 + r) * KP + k0 + sg * 8;
            uint32_t d = ab + (var ? OFF_ALO_ : 0) + swz((uint32_t)(r * 128 + sg * 16));
            cp16(d, g, (m0 + r) < NN);
        }
#pragma unroll
        for (int it = 0; it < BNT * 16 / 512; it++) {  // B: BNT*16 cp16
            int i = tid + it * 512;
            int var = i / (BNT * 8);
            int j = i % (BNT * 8);
            int r = j >> 3, sg = j & 7;
            const __nv_bfloat16* base = var ? Blo : Bhi;
            const void* g = base + (size_t)(n0 + r) * KP + k0 + sg * 8;
            uint32_t d = ab + (var ? OFF_BLO_ : OFF_BHI_) + swz((uint32_t)(r * 128 + sg * 16));
            cp16(d, g, true);
        }
    };

    int lr = lane & 15;
    int lc = ((lane >> 4) & 1) * 16;

    auto compute = [&](int s) {
        uint32_t ab = dynb + s * STAGE_;
#pragma unroll
        for (int ks = 0; ks < 4; ks++) {
            int kb = ks * 32;
            uint32_t ah[MI][4], al[MI][4];
#pragma unroll
            for (int mi = 0; mi < MI; mi++) {
                uint32_t off = swz((uint32_t)((wm * MT_W + mi * 16 + lr) * 128 + kb + lc));
                ldsm_x4(ah[mi], ab + off);
                ldsm_x4(al[mi], ab + OFF_ALO_ + off);
            }
            uint32_t bh[2][4], bl[2][4];
#pragma unroll
            for (int bi = 0; bi < 2; bi++) {
                uint32_t off = swz((uint32_t)((wn * 32 + bi * 16 + lr) * 128 + kb + lc));
                ldsm_x4(bh[bi], ab + OFF_BHI_ + off);
                ldsm_x4(bl[bi], ab + OFF_BLO_ + off);
            }
#pragma unroll
            for (int mi = 0; mi < MI; mi++) {
#pragma unroll
                for (int t = 0; t < 4; t++) {
                    uint32_t bfh[2] = { bh[t >> 1][t & 1], bh[t >> 1][(t & 1) + 2] };
                    uint32_t bfl[2] = { bl[t >> 1][t & 1], bl[t >> 1][(t & 1) + 2] };
                    mma_bf16(acc[mi][t], ah[mi], bfh);
                    mma_bf16(acc[mi][t], al[mi], bfh);
                    mma_bf16(acc[mi][t], ah[mi], bfl);
                }
            }
        }
    };

    load_stage(0, 0);
    CP_COMMIT();
    if (nk > 1) load_stage(1, 1);
    CP_COMMIT();
    for (int kt = 0; kt < nk; kt++) {
        CP_WAIT1();
        __syncthreads();
        if (kt + 2 < nk) load_stage((kt + 2) % 3, kt + 2);
        CP_COMMIT();
        compute(kt % 3);
    }

    // ---------------- epilogue ----------------
    int lrow = lane >> 2;
    int lcol = (lane & 3) * 2;

    if (MODE == 0) {
#pragma unroll
        for (int mi = 0; mi < MI; mi++) {
            int gm = m0 + wm * MT_W + mi * 16 + lrow;
#pragma unroll
            for (int t = 0; t < 4; t++) {
                int c = wn * 32 + t * 8 + lcol;
                float b0 = s_bias[c], b1 = s_bias[c + 1];
                int cg = n0 + c;
#pragma unroll
                for (int rr = 0; rr < 2; rr++) {
                    int g = gm + rr * 8;
                    if (g < NN) {
                        float v0 = fmaxf(acc[mi][t][rr * 2 + 0] + b0, 0.f);
                        float v1 = fmaxf(acc[mi][t][rr * 2 + 1] + b1, 0.f);
                        __nv_bfloat16 h0 = __float2bfloat16(v0), h1 = __float2bfloat16(v1);
                        float r0 = v0 - __bfloat162float(h0);
                        float r1 = v1 - __bfloat162float(h1);
                        __nv_bfloat16 l0 = __float2bfloat16(r0), l1 = __float2bfloat16(r1);
                        uint32_t hp = (uint32_t)__bfloat16_as_ushort(h0) |
                                      ((uint32_t)__bfloat16_as_ushort(h1) << 16);
                        uint32_t lp = (uint32_t)__bfloat16_as_ushort(l0) |
                                      ((uint32_t)__bfloat16_as_ushort(l1) << 16);
                        *(uint32_t*)(Ohi + (size_t)g * NP1 + cg) = hp;
                        *(uint32_t*)(Olo + (size_t)g * NP1 + cg) = lp;
                    }
                }
            }
        }
    } else {
#pragma unroll
        for (int t = 0; t < 4; t++) {
            int c = wn * 32 + t * 8 + lcol;
            int cg = n0 + c;
            float b0 = s_bias[c], b1 = s_bias[c + 1];
            float s0 = 0.f, s1 = 0.f, q0 = 0.f, q1 = 0.f;
#pragma unroll
            for (int mi = 0; mi < MI; mi++) {
                int gm = m0 + wm * MT_W + mi * 16 + lrow;
                float v0 = acc[mi][t][0] + b0, v1 = acc[mi][t][1] + b1;
                float v2 = acc[mi][t][2] + b0, v3 = acc[mi][t][3] + b1;
                if (gm >= NN) { v0 = 0.f; v1 = 0.f; }
                if (gm + 8 >= NN) { v2 = 0.f; v3 = 0.f; }
                if (cg < HP) {
                    if (gm < NN) *(float2*)(H + (size_t)gm * HP + cg) = make_float2(v0, v1);
                    if (gm + 8 < NN) *(float2*)(H + (size_t)(gm + 8) * HP + cg) = make_float2(v2, v3);
                }
                s0 += v0 + v2; s1 += v1 + v3;
                q0 += v0 * v0 + v2 * v2; q1 += v1 * v1 + v3 * v3;
            }
#pragma unroll
            for (int off = 4; off < 32; off <<= 1) {
                s0 += __shfl_xor_sync(0xffffffffu, s0, off);
                s1 += __shfl_xor_sync(0xffffffffu, s1, off);
                q0 += __shfl_xor_sync(0xffffffffu, q0, off);
                q1 += __shfl_xor_sync(0xffffffffu, q1, off);
            }
            if (lane < 4) {
                if (cg < DEMB) { atomicAdd(&s_sum[c], s0); atomicAdd(&s_sq[c], q0); }
                if (cg + 1 < DEMB) { atomicAdd(&s_sum[c + 1], s1); atomicAdd(&s_sq[c + 1], q1); }
            }
        }
        __syncthreads();
        if (tid < BNT) {
            int n = n0 + tid;
            if (n < DEMB) {
                atomicAdd(&colsum[n], s_sum[tid]);
                atomicAdd(&colsq[n], s_sq[tid]);
            }
        }
    }
}

// ---------------- BN finalize ----------------
__global__ void k_bnfin(const float* __restrict__ gamma, const float* __restrict__ beta) {
    int f = threadIdx.x;
    if (f >= DEMB) return;
    const float invM = 1.0f / (float)NN;
    float mu = g_colsum[f] * invM;
    float var = g_colsq[f] * invM - mu * mu;
    float a = gamma[f] * rsqrtf(var + BN_EPS);
    g_a[f] = a;
    g_c[f] = beta[f] - mu * a;
}

// ---------------- pooling ----------------
#define POOL_TILE 32
__global__ void k_pool(const int* __restrict__ gid) {
    int f = blockIdx.y * 128 + threadIdx.x;
    if (f >= DEMB) return;
    int n0 = blockIdx.x * POOL_TILE;
    float acc = 0.f;
    int cur = gid[n0];
    for (int i = 0; i < POOL_TILE; i++) {
        int n = n0 + i;
        int g = gid[n];
        if (g != cur) {
            atomicAdd(&g_pool[cur * DEMB + f], acc);
            acc = 0.f;
            cur = g;
        }
        acc += g_h[(size_t)n * HP + f];
    }
    atomicAdd(&g_pool[cur * DEMB + f], acc);
}

// ---------------- final ----------------
__global__ void k_final(const float* __restrict__ wt, const float* __restrict__ bt,
                        float* __restrict__ out) {
    int g = blockIdx.x;
    int o = threadIdx.x;
    float cnt = g_cnt[g];
    float inv = 1.0f / fmaxf(cnt, 1.f);
    float acc = 0.f;
    for (int f = 0; f < DEMB; f++) {
        float pf = (g_a[f] * g_pool[g * DEMB + f] + cnt * g_c[f]) * inv;
        acc += pf * wt[f * DOUT + o];
    }
    out[g * DOUT + o] = acc + bt[o];
}

// ---------------- host launcher ----------------
#define GSMEM128 (3 * (32768 + 2 * 128 * 128) + 1024)
#define GSMEM64  (3 * (32768 + 2 * 64 * 128) + 1024)

extern "C" void kernel_launch(void* const* d_in, const int* in_sizes, int n_in,
                              void* d_out, int out_size) {
    const float* node_feats = (const float*)d_in[0];
    const float* edge_feats = (const float*)d_in[1];
    const int*   src        = (const int*)d_in[2];
    const int*   dst        = (const int*)d_in[3];
    const int*   gid        = (const int*)d_in[4];
    const float* w1_0  = (const float*)d_in[5];
    const float* b1_0  = (const float*)d_in[6];
    const float* w2_0  = (const float*)d_in[7];
    const float* b2_0  = (const float*)d_in[8];
    const float* gamma0 = (const float*)d_in[9];
    const float* beta0  = (const float*)d_in[10];
    const float* w1   = (const float*)d_in[11];
    const float* b1   = (const float*)d_in[12];
    const float* w2   = (const float*)d_in[13];
    const float* b2   = (const float*)d_in[14];
    const float* gamma = (const float*)d_in[15];
    const float* beta  = (const float*)d_in[16];
    const float* wt   = (const float*)d_in[17];
    const float* bt   = (const float*)d_in[18];
    float* out = (float*)d_out;

    static bool attr_done = false;
    if (!attr_done) {
        cudaFuncSetAttribute(k_gemm<0, 128>, cudaFuncAttributeMaxDynamicSharedMemorySize, GSMEM128);
        cudaFuncSetAttribute(k_gemm<1, 128>, cudaFuncAttributeMaxDynamicSharedMemorySize, GSMEM128);
        cudaFuncSetAttribute(k_gemm<1, 64>,  cudaFuncAttributeMaxDynamicSharedMemorySize, GSMEM64);
        attr_done = true;
    }

    __nv_bfloat16 *p_ahi, *p_alo, *p_thi, *p_tlo, *p_w1hi, *p_w1lo, *p_w2hi, *p_w2lo;
    float *p_h, *p_b1p, *p_b2p, *p_colsum, *p_colsq;
    cudaGetSymbolAddress((void**)&p_ahi, g_ahi);
    cudaGetSymbolAddress((void**)&p_alo, g_alo);
    cudaGetSymbolAddress((void**)&p_thi, g_thi);
    cudaGetSymbolAddress((void**)&p_tlo, g_tlo);
    cudaGetSymbolAddress((void**)&p_w1hi, g_w1hi);
    cudaGetSymbolAddress((void**)&p_w1lo, g_w1lo);
    cudaGetSymbolAddress((void**)&p_w2hi, g_w2hi);
    cudaGetSymbolAddress((void**)&p_w2lo, g_w2lo);
    cudaGetSymbolAddress((void**)&p_h, g_h);
    cudaGetSymbolAddress((void**)&p_b1p, g_b1p);
    cudaGetSymbolAddress((void**)&p_b2p, g_b2p);
    cudaGetSymbolAddress((void**)&p_colsum, g_colsum);
    cudaGetSymbolAddress((void**)&p_colsq, g_colsq);

    // ---- preprocessing ----
    k_prepw<<<(NP1 * KP0 + 255) / 256, 256>>>(w1_0, b1_0, DIN, DHID, KP0, NP1,
                                              p_w1hi, p_w1lo, p_b1p);
    k_prepw<<<(NP2 * KP2 + 255) / 256, 256>>>(w2_0, b2_0, DHID, DEMB, KP2, NP2,
                                              p_w2hi, p_w2lo, p_b2p);
    k_zero_pre<<<(NN + 255) / 256, 256>>>();
    k_zero_pool<<<(GG * DEMB + 255) / 256, 256>>>();
    k_edge_prep<<<(EE + 255) / 256, 256>>>(dst, edge_feats);
    k_scan1<<<SCAN_NB, 1024>>>();
    k_scan2<<<1, 128>>>();
    k_scan3<<<SCAN_NB, 1024>>>();
    k_edge_fill<<<(EE + 255) / 256, 256>>>(src, dst);
    k_counts<<<(NN + 255) / 256, 256>>>(gid);

    const int MT = (NN + BM - 1) / BM;       // 782
    dim3 grid1(MT, NP1 / 128);               // (782, 5)
    dim3 grid2a(MT, 2);                      // n0 0,128
    dim3 grid2b(MT, 1);                      // n0 256 (64 wide)

    // ---- layer 0 ----
    k_spmm0<<<(NN * 32 + 255) / 256, 256>>>(node_feats);
    k_zero_stats<<<1, 320>>>();
    k_gemm<0, 128><<<grid1, 512, GSMEM128>>>(p_ahi, p_alo, KP0, p_w1hi, p_w1lo, p_b1p,
                                             KP0 / BK, 0, p_thi, p_tlo, nullptr, nullptr, nullptr);
    k_gemm<1, 128><<<grid2a, 512, GSMEM128>>>(p_thi, p_tlo, KP2, p_w2hi, p_w2lo, p_b2p,
                                              KP2 / BK, 0, nullptr, nullptr, p_h, p_colsum, p_colsq);
    k_gemm<1, 64><<<grid2b, 512, GSMEM64>>>(p_thi, p_tlo, KP2, p_w2hi, p_w2lo, p_b2p,
                                            KP2 / BK, 256, nullptr, nullptr, p_h, p_colsum, p_colsq);
    k_bnfin<<<1, 320>>>(gamma0, beta0);

    // ---- layers 1..4 ----
    for (int l = 0; l < 4; l++) {
        k_prepw<<<(NP1 * KP1 + 255) / 256, 256>>>(w1 + (size_t)l * DEMB * DHID,
                                                  b1 + (size_t)l * DHID, DEMB, DHID, KP1, NP1,
                                                  p_w1hi, p_w1lo, p_b1p);
        k_prepw<<<(NP2 * KP2 + 255) / 256, 256>>>(w2 + (size_t)l * DHID * DEMB,
                                                  b2 + (size_t)l * DEMB, DHID, DEMB, KP2, NP2,
                                                  p_w2hi, p_w2lo, p_b2p);
        k_spmm300<<<NN, 128>>>();
        k_zero_stats<<<1, 320>>>();
        k_gemm<0, 128><<<grid1, 512, GSMEM128>>>(p_ahi, p_alo, KP1, p_w1hi, p_w1lo, p_b1p,
                                                 KP1 / BK, 0, p_thi, p_tlo, nullptr, nullptr, nullptr);
        k_gemm<1, 128><<<grid2a, 512, GSMEM128>>>(p_thi, p_tlo, KP2, p_w2hi, p_w2lo, p_b2p,
                                                  KP2 / BK, 0, nullptr, nullptr, p_h, p_colsum, p_colsq);
        k_gemm<1, 64><<<grid2b, 512, GSMEM64>>>(p_thi, p_tlo, KP2, p_w2hi, p_w2lo, p_b2p,
                                                KP2 / BK, 256, nullptr, nullptr, p_h, p_colsum, p_colsq);
        k_bnfin<<<1, 320>>>(gamma + (size_t)l * DEMB, beta + (size_t)l * DEMB);
    }

    // ---- readout ----
    k_pool<<<dim3(NN / POOL_TILE, (DEMB + 127) / 128), 128>>>(gid);
    k_final<<<GG, DOUT>>>(wt, bt, out);
}

// round 5
// speedup vs baseline: 2.6681x; 1.1644x over previous
#include <cuda_runtime.h>
#include <cuda_fp16.h>
#include <math.h>
#include <stdint.h>

#define NN   100000
#define EE   1600000
#define GG   128
#define DEMB 300
#define DHID 600
#define DIN  20
#define DOUT 64
#define BN_EPS 1e-5f

#define SPLIT_S   0.015625f   // 2^-6
#define SPLIT_INV 64.0f
#define SPLIT_1MS 0.984375f   // 1 - 2^-6

// padded dims
#define KP1   320
#define KP0   64
#define NP1   640
#define KP2   640
#define NP2   320
#define HP    320

// ---------------- scratch (device globals) ----------------
__device__ float  g_h[(size_t)NN * HP];
__device__ __half g_ah[(size_t)NN * KP1];   // A hi (fp16)
__device__ __half g_ap[(size_t)NN * KP1];   // A P-term
__device__ __half g_th[(size_t)NN * NP1];   // hidden hi / GEMM2 A hi
__device__ __half g_tp[(size_t)NN * NP1];
__device__ __half g_w1h[NP1 * KP1];
__device__ __half g_w1q[NP1 * KP1];
__device__ float  g_b1p[NP1];
__device__ __half g_w2h[NP2 * KP2];
__device__ __half g_w2q[NP2 * KP2];
__device__ float  g_b2p[NP2];

__device__ int   g_rowptr[NN + 1];
__device__ int   g_deg[NN];
__device__ int   g_cursor[NN];
__device__ int   g_csrc[EE];
__device__ float g_esum[NN];
__device__ int   g_blksum[128];
__device__ int   g_blkoff[128];
__device__ float g_colsum[DEMB];
__device__ float g_colsq[DEMB];
__device__ float g_a[DEMB];
__device__ float g_c[DEMB];
__device__ float g_pool[GG * DEMB];
__device__ float g_cnt[GG];

#define SCAN_NB ((NN + 1023) / 1024)

// ---------------- PTX helpers ----------------
__device__ __forceinline__ uint32_t smem_u32(const void* p) {
    uint32_t a;
    asm("{ .reg .u64 t; cvta.to.shared.u64 t, %1; cvt.u32.u64 %0, t; }" : "=r"(a) : "l"(p));
    return a;
}
__device__ __forceinline__ void cp16(uint32_t d, const void* g, bool pred) {
    int sz = pred ? 16 : 0;
    asm volatile("cp.async.cg.shared.global [%0], [%1], 16, %2;"
                 :: "r"(d), "l"(g), "r"(sz) : "memory");
}
#define CP_COMMIT() asm volatile("cp.async.commit_group;" ::: "memory")
#define CP_WAIT1()  asm volatile("cp.async.wait_group 1;" ::: "memory")

__device__ __forceinline__ void ldsm_x4(uint32_t* r, uint32_t a) {
    asm volatile("ldmatrix.sync.aligned.m8n8.x4.shared.b16 {%0,%1,%2,%3}, [%4];"
                 : "=r"(r[0]), "=r"(r[1]), "=r"(r[2]), "=r"(r[3]) : "r"(a));
}
__device__ __forceinline__ void mma_f16(float* c, const uint32_t* a, const uint32_t* b) {
    asm volatile(
        "mma.sync.aligned.m16n8k16.row.col.f32.f16.f16.f32 "
        "{%0,%1,%2,%3}, {%4,%5,%6,%7}, {%8,%9}, {%0,%1,%2,%3};"
        : "+f"(c[0]), "+f"(c[1]), "+f"(c[2]), "+f"(c[3])
        : "r"(a[0]), "r"(a[1]), "r"(a[2]), "r"(a[3]), "r"(b[0]), "r"(b[1]));
}
__device__ __forceinline__ uint32_t swz(uint32_t off) { return off ^ ((off >> 3) & 0x70); }

// producer split: hi = fp16(v), p = fp16((v-hi) + s*hi)
__device__ __forceinline__ void split2(float v, __half& h, __half& p) {
    h = __float2half_rn(v);
    float hf = __half2float(h);
    p = __float2half_rn((v - hf) + SPLIT_S * hf);
}

// ---------------- preprocessing kernels ----------------
__global__ void k_zero_pre() {
    int i = blockIdx.x * blockDim.x + threadIdx.x;
    if (i < NN) { g_deg[i] = 0; g_cursor[i] = 0; g_esum[i] = 0.f; }
}
__global__ void k_zero_pool() {
    int i = blockIdx.x * blockDim.x + threadIdx.x;
    if (i < GG * DEMB) g_pool[i] = 0.f;
    if (i < GG) g_cnt[i] = 0.f;
}
__global__ void k_zero_stats() {
    int i = threadIdx.x;
    if (i < DEMB) { g_colsum[i] = 0.f; g_colsq[i] = 0.f; }
}
__global__ void k_edge_prep(const int* __restrict__ dst, const float* __restrict__ ef) {
    int e = blockIdx.x * blockDim.x + threadIdx.x;
    if (e < EE) {
        int d = dst[e];
        atomicAdd(&g_deg[d], 1);
        atomicAdd(&g_esum[d], ef[e]);
    }
}
__global__ void k_scan1() {
    __shared__ int sh[1024];
    int b = blockIdx.x;
    int i = b * 1024 + threadIdx.x;
    int v = (i < NN) ? g_deg[i] : 0;
    sh[threadIdx.x] = v;
    __syncthreads();
#pragma unroll
    for (int off = 1; off < 1024; off <<= 1) {
        int t = (threadIdx.x >= off) ? sh[threadIdx.x - off] : 0;
        __syncthreads();
        sh[threadIdx.x] += t;
        __syncthreads();
    }
    if (i < NN) g_rowptr[i] = sh[threadIdx.x] - v;
    if (threadIdx.x == 1023) g_blksum[b] = sh[1023];
}
__global__ void k_scan2() {
    __shared__ int sh[128];
    int t = threadIdx.x;
    int v = (t < SCAN_NB) ? g_blksum[t] : 0;
    sh[t] = v;
    __syncthreads();
#pragma unroll
    for (int off = 1; off < 128; off <<= 1) {
        int x = (t >= off) ? sh[t - off] : 0;
        __syncthreads();
        sh[t] += x;
        __syncthreads();
    }
    if (t < SCAN_NB) g_blkoff[t] = sh[t] - v;
    if (t == 0) g_rowptr[NN] = EE;
}
__global__ void k_scan3() {
    int b = blockIdx.x;
    int i = b * 1024 + threadIdx.x;
    if (i < NN) g_rowptr[i] += g_blkoff[b];
}
__global__ void k_edge_fill(const int* __restrict__ src, const int* __restrict__ dst) {
    int e = blockIdx.x * blockDim.x + threadIdx.x;
    if (e < EE) {
        int d = dst[e];
        int pos = atomicAdd(&g_cursor[d], 1);
        g_csrc[g_rowptr[d] + pos] = src[e];
    }
}
__global__ void k_counts(const int* __restrict__ gid) {
    int n = blockIdx.x * blockDim.x + threadIdx.x;
    if (n < NN) atomicAdd(&g_cnt[gid[n]], 1.f);
}

// ---------------- weight prep: transpose + pad + fp16 compensated split ----------------
__global__ void k_prepw(const float* __restrict__ w, const float* __restrict__ bias,
                        int K, int Nn, int KPp, int NPp,
                        __half* __restrict__ whT, __half* __restrict__ wqT,
                        float* __restrict__ bp) {
    int idx = blockIdx.x * blockDim.x + threadIdx.x;
    if (idx >= NPp * KPp) return;
    int nrow = idx / KPp, k = idx - nrow * KPp;
    float v = (nrow < Nn && k < K) ? w[(size_t)k * Nn + nrow] : 0.f;
    __half hi = __float2half_rn(v);
    float hf = __half2float(hi);
    whT[idx] = hi;
    wqT[idx] = __float2half_rn(hf + (v - hf) * SPLIT_INV);  // Q = Bhi + Blo/s
    if (k == 0) bp[nrow] = (nrow < Nn) ? bias[nrow] : 0.f;
}

// ---------------- SpMM kernels (emit fp16 hi/P) ----------------
__global__ void k_spmm0(const float* __restrict__ x) {
    int warp = (blockIdx.x * blockDim.x + threadIdx.x) >> 5;
    int lane = threadIdx.x & 31;
    if (warp >= NN) return;
    int beg = g_rowptr[warp], end = g_rowptr[warp + 1];
    float s = 0.f;
    for (int j = beg; j < end; j++) {
        int sn = g_csrc[j];
        if (lane < DIN) s += x[sn * DIN + lane];
    }
    float v0 = (lane < DIN) ? (s + g_esum[warp]) : 0.f;
    size_t o = (size_t)warp * KP0;
    __half h, p;
    split2(v0, h, p);
    g_ah[o + lane] = h;
    g_ap[o + lane] = p;
    g_ah[o + lane + 32] = __float2half_rn(0.f);
    g_ap[o + lane + 32] = __float2half_rn(0.f);
}

__global__ void k_spmm300() {
    int n = blockIdx.x;
    int t = threadIdx.x;  // 128
    int beg = g_rowptr[n], end = g_rowptr[n + 1];
    float s0 = 0.f, s1 = 0.f, s2 = 0.f;
    for (int j = beg; j < end; j++) {
        const float* row = g_h + (size_t)g_csrc[j] * HP;
        s0 += row[t];
        s1 += row[t + 128];
        if (t < DEMB - 256) s2 += row[t + 256];
    }
    float es = g_esum[n];
    float dg = (float)(end - beg);
    size_t o = (size_t)n * KP1;
    float v0 = g_a[t] * s0 + dg * g_c[t] + es;
    float v1 = g_a[t + 128] * s1 + dg * g_c[t + 128] + es;
    __half h0, p0, h1, p1;
    split2(v0, h0, p0);
    split2(v1, h1, p1);
    g_ah[o + t] = h0;       g_ap[o + t] = p0;
    g_ah[o + t + 128] = h1; g_ap[o + t + 128] = p1;
    if (t + 256 < KP1) {
        float v2 = (t + 256 < DEMB) ? (g_a[t + 256] * s2 + dg * g_c[t + 256] + es) : 0.f;
        __half h2, p2;
        split2(v2, h2, p2);
        g_ah[o + t + 256] = h2;
        g_ap[o + t + 256] = p2;
    }
}

// ---------------- fp16 2-MMA compensated GEMM, 512 threads ----------------
// acc1 = Ahi*Bhi ; acc2 = P*Q ; D = (1-s)*acc1 + acc2
// MODE 0: bias + ReLU -> Oh/Op fp16 (pitch NP1)
// MODE 1: bias -> H fp32 (cols<HP) + column stats (cols<DEMB)
#define BM 128
#define BK 64

template <int MODE, int BNT>
__global__ __launch_bounds__(512, 1) void k_gemm(
    const __half* __restrict__ Ah, const __half* __restrict__ Ap, int KP,
    const __half* __restrict__ Bh, const __half* __restrict__ Bq,
    const float* __restrict__ biasp, int nk, int n0_base,
    __half* __restrict__ Oh, __half* __restrict__ Op,
    float* __restrict__ H, float* __restrict__ colsum, float* __restrict__ colsq) {
    constexpr int WN_W = BNT / 32;
    constexpr int WM_W = 16 / WN_W;
    constexpr int MT_W = BM / WM_W;
    constexpr int MI   = MT_W / 16;
    constexpr int OFF_AP_ = 16384;
    constexpr int OFF_BH_ = 32768;
    constexpr int OFF_BQ_ = 32768 + BNT * 128;
    constexpr int STAGE_  = 32768 + 2 * BNT * 128;

    extern __shared__ char dyn[];
    __shared__ float s_bias[128];
    __shared__ float s_sum[128], s_sq[128];

    int tid = threadIdx.x;
    int wid = tid >> 5;
    int lane = tid & 31;
    int wm = wid / WN_W;
    int wn = wid % WN_W;
    int m0 = blockIdx.x * BM;
    int n0 = n0_base + blockIdx.y * BNT;

    uint32_t dynb0 = smem_u32(dyn);
    uint32_t dynb = (dynb0 + 1023u) & ~1023u;

    if (tid < BNT) {
        s_bias[tid] = biasp[n0 + tid];
        if (MODE == 1) { s_sum[tid] = 0.f; s_sq[tid] = 0.f; }
    }

    float acc1[MI][4][4] = {};
    float acc2[MI][4][4] = {};

    auto load_stage = [&](int s, int kt) {
        uint32_t ab = dynb + s * STAGE_;
        int k0 = kt * BK;
#pragma unroll
        for (int it = 0; it < 4; it++) {
            int i = tid + it * 512;
            int var = i >> 10;
            int j = i & 1023;
            int r = j >> 3, sg = j & 7;
            const __half* base = var ? Ap : Ah;
            const void* g = base + (size_t)(m0 + r) * KP + k0 + sg * 8;
            uint32_t d = ab + (var ? OFF_AP_ : 0) + swz((uint32_t)(r * 128 + sg * 16));
            cp16(d, g, (m0 + r) < NN);
        }
#pragma unroll
        for (int it = 0; it < BNT * 16 / 512; it++) {
            int i = tid + it * 512;
            int var = i / (BNT * 8);
            int j = i % (BNT * 8);
            int r = j >> 3, sg = j & 7;
            const __half* base = var ? Bq : Bh;
            const void* g = base + (size_t)(n0 + r) * KP + k0 + sg * 8;
            uint32_t d = ab + (var ? OFF_BQ_ : OFF_BH_) + swz((uint32_t)(r * 128 + sg * 16));
            cp16(d, g, true);
        }
    };

    int lr = lane & 15;
    int lc = ((lane >> 4) & 1) * 16;

    auto compute = [&](int s) {
        uint32_t ab = dynb + s * STAGE_;
#pragma unroll
        for (int ks = 0; ks < 4; ks++) {
            int kb = ks * 32;
            uint32_t ah[MI][4], ap[MI][4];
#pragma unroll
            for (int mi = 0; mi < MI; mi++) {
                uint32_t off = swz((uint32_t)((wm * MT_W + mi * 16 + lr) * 128 + kb + lc));
                ldsm_x4(ah[mi], ab + off);
                ldsm_x4(ap[mi], ab + OFF_AP_ + off);
            }
            uint32_t bh[2][4], bq[2][4];
#pragma unroll
            for (int bi = 0; bi < 2; bi++) {
                uint32_t off = swz((uint32_t)((wn * 32 + bi * 16 + lr) * 128 + kb + lc));
                ldsm_x4(bh[bi], ab + OFF_BH_ + off);
                ldsm_x4(bq[bi], ab + OFF_BQ_ + off);
            }
#pragma unroll
            for (int mi = 0; mi < MI; mi++) {
#pragma unroll
                for (int t = 0; t < 4; t++) {
                    uint32_t bfh[2] = { bh[t >> 1][t & 1], bh[t >> 1][(t & 1) + 2] };
                    uint32_t bfq[2] = { bq[t >> 1][t & 1], bq[t >> 1][(t & 1) + 2] };
                    mma_f16(acc1[mi][t], ah[mi], bfh);
                    mma_f16(acc2[mi][t], ap[mi], bfq);
                }
            }
        }
    };

    load_stage(0, 0);
    CP_COMMIT();
    if (nk > 1) load_stage(1, 1);
    CP_COMMIT();
    for (int kt = 0; kt < nk; kt++) {
        CP_WAIT1();
        __syncthreads();
        if (kt + 2 < nk) load_stage((kt + 2) % 3, kt + 2);
        CP_COMMIT();
        compute(kt % 3);
    }

    // ---------------- epilogue ----------------
    int lrow = lane >> 2;
    int lcol = (lane & 3) * 2;

    if (MODE == 0) {
#pragma unroll
        for (int mi = 0; mi < MI; mi++) {
            int gm = m0 + wm * MT_W + mi * 16 + lrow;
#pragma unroll
            for (int t = 0; t < 4; t++) {
                int c = wn * 32 + t * 8 + lcol;
                float b0 = s_bias[c], b1 = s_bias[c + 1];
                int cg = n0 + c;
#pragma unroll
                for (int rr = 0; rr < 2; rr++) {
                    int g = gm + rr * 8;
                    if (g < NN) {
                        float v0 = fmaxf(SPLIT_1MS * acc1[mi][t][rr * 2 + 0] +
                                         acc2[mi][t][rr * 2 + 0] + b0, 0.f);
                        float v1 = fmaxf(SPLIT_1MS * acc1[mi][t][rr * 2 + 1] +
                                         acc2[mi][t][rr * 2 + 1] + b1, 0.f);
                        __half h0, p0, h1, p1;
                        split2(v0, h0, p0);
                        split2(v1, h1, p1);
                        uint32_t hp = (uint32_t)__half_as_ushort(h0) |
                                      ((uint32_t)__half_as_ushort(h1) << 16);
                        uint32_t pp = (uint32_t)__half_as_ushort(p0) |
                                      ((uint32_t)__half_as_ushort(p1) << 16);
                        *(uint32_t*)(Oh + (size_t)g * NP1 + cg) = hp;
                        *(uint32_t*)(Op + (size_t)g * NP1 + cg) = pp;
                    }
                }
            }
        }
    } else {
#pragma unroll
        for (int t = 0; t < 4; t++) {
            int c = wn * 32 + t * 8 + lcol;
            int cg = n0 + c;
            float b0 = s_bias[c], b1 = s_bias[c + 1];
            float s0 = 0.f, s1 = 0.f, q0 = 0.f, q1 = 0.f;
#pragma unroll
            for (int mi = 0; mi < MI; mi++) {
                int gm = m0 + wm * MT_W + mi * 16 + lrow;
                float v0 = SPLIT_1MS * acc1[mi][t][0] + acc2[mi][t][0] + b0;
                float v1 = SPLIT_1MS * acc1[mi][t][1] + acc2[mi][t][1] + b1;
                float v2 = SPLIT_1MS * acc1[mi][t][2] + acc2[mi][t][2] + b0;
                float v3 = SPLIT_1MS * acc1[mi][t][3] + acc2[mi][t][3] + b1;
                if (gm >= NN) { v0 = 0.f; v1 = 0.f; }
                if (gm + 8 >= NN) { v2 = 0.f; v3 = 0.f; }
                if (cg < HP) {
                    if (gm < NN) *(float2*)(H + (size_t)gm * HP + cg) = make_float2(v0, v1);
                    if (gm + 8 < NN) *(float2*)(H + (size_t)(gm + 8) * HP + cg) = make_float2(v2, v3);
                }
                s0 += v0 + v2; s1 += v1 + v3;
                q0 += v0 * v0 + v2 * v2; q1 += v1 * v1 + v3 * v3;
            }
#pragma unroll
            for (int off = 4; off < 32; off <<= 1) {
                s0 += __shfl_xor_sync(0xffffffffu, s0, off);
                s1 += __shfl_xor_sync(0xffffffffu, s1, off);
                q0 += __shfl_xor_sync(0xffffffffu, q0, off);
                q1 += __shfl_xor_sync(0xffffffffu, q1, off);
            }
            if (lane < 4) {
                if (cg < DEMB) { atomicAdd(&s_sum[c], s0); atomicAdd(&s_sq[c], q0); }
                if (cg + 1 < DEMB) { atomicAdd(&s_sum[c + 1], s1); atomicAdd(&s_sq[c + 1], q1); }
            }
        }
        __syncthreads();
        if (tid < BNT) {
            int n = n0 + tid;
            if (n < DEMB) {
                atomicAdd(&colsum[n], s_sum[tid]);
                atomicAdd(&colsq[n], s_sq[tid]);
            }
        }
    }
}

// ---------------- BN finalize ----------------
__global__ void k_bnfin(const float* __restrict__ gamma, const float* __restrict__ beta) {
    int f = threadIdx.x;
    if (f >= DEMB) return;
    const float invM = 1.0f / (float)NN;
    float mu = g_colsum[f] * invM;
    float var = g_colsq[f] * invM - mu * mu;
    float a = gamma[f] * rsqrtf(var + BN_EPS);
    g_a[f] = a;
    g_c[f] = beta[f] - mu * a;
}

// ---------------- pooling ----------------
#define POOL_TILE 32
__global__ void k_pool(const int* __restrict__ gid) {
    int f = blockIdx.y * 128 + threadIdx.x;
    if (f >= DEMB) return;
    int n0 = blockIdx.x * POOL_TILE;
    float acc = 0.f;
    int cur = gid[n0];
    for (int i = 0; i < POOL_TILE; i++) {
        int n = n0 + i;
        int g = gid[n];
        if (g != cur) {
            atomicAdd(&g_pool[cur * DEMB + f], acc);
            acc = 0.f;
            cur = g;
        }
        acc += g_h[(size_t)n * HP + f];
    }
    atomicAdd(&g_pool[cur * DEMB + f], acc);
}

// ---------------- final ----------------
__global__ void k_final(const float* __restrict__ wt, const float* __restrict__ bt,
                        float* __restrict__ out) {
    int g = blockIdx.x;
    int o = threadIdx.x;
    float cnt = g_cnt[g];
    float inv = 1.0f / fmaxf(cnt, 1.f);
    float acc = 0.f;
    for (int f = 0; f < DEMB; f++) {
        float pf = (g_a[f] * g_pool[g * DEMB + f] + cnt * g_c[f]) * inv;
        acc += pf * wt[f * DOUT + o];
    }
    out[g * DOUT + o] = acc + bt[o];
}

// ---------------- host launcher ----------------
#define GSMEM128 (3 * (32768 + 2 * 128 * 128) + 1024)
#define GSMEM64  (3 * (32768 + 2 * 64 * 128) + 1024)

extern "C" void kernel_launch(void* const* d_in, const int* in_sizes, int n_in,
                              void* d_out, int out_size) {
    const float* node_feats = (const float*)d_in[0];
    const float* edge_feats = (const float*)d_in[1];
    const int*   src        = (const int*)d_in[2];
    const int*   dst        = (const int*)d_in[3];
    const int*   gid        = (const int*)d_in[4];
    const float* w1_0  = (const float*)d_in[5];
    const float* b1_0  = (const float*)d_in[6];
    const float* w2_0  = (const float*)d_in[7];
    const float* b2_0  = (const float*)d_in[8];
    const float* gamma0 = (const float*)d_in[9];
    const float* beta0  = (const float*)d_in[10];
    const float* w1   = (const float*)d_in[11];
    const float* b1   = (const float*)d_in[12];
    const float* w2   = (const float*)d_in[13];
    const float* b2   = (const float*)d_in[14];
    const float* gamma = (const float*)d_in[15];
    const float* beta  = (const float*)d_in[16];
    const float* wt   = (const float*)d_in[17];
    const float* bt   = (const float*)d_in[18];
    float* out = (float*)d_out;

    static bool attr_done = false;
    if (!attr_done) {
        cudaFuncSetAttribute(k_gemm<0, 128>, cudaFuncAttributeMaxDynamicSharedMemorySize, GSMEM128);
        cudaFuncSetAttribute(k_gemm<1, 128>, cudaFuncAttributeMaxDynamicSharedMemorySize, GSMEM128);
        cudaFuncSetAttribute(k_gemm<1, 64>,  cudaFuncAttributeMaxDynamicSharedMemorySize, GSMEM64);
        attr_done = true;
    }

    __half *p_ah, *p_ap, *p_th, *p_tp, *p_w1h, *p_w1q, *p_w2h, *p_w2q;
    float *p_h, *p_b1p, *p_b2p, *p_colsum, *p_colsq;
    cudaGetSymbolAddress((void**)&p_ah, g_ah);
    cudaGetSymbolAddress((void**)&p_ap, g_ap);
    cudaGetSymbolAddress((void**)&p_th, g_th);
    cudaGetSymbolAddress((void**)&p_tp, g_tp);
    cudaGetSymbolAddress((void**)&p_w1h, g_w1h);
    cudaGetSymbolAddress((void**)&p_w1q, g_w1q);
    cudaGetSymbolAddress((void**)&p_w2h, g_w2h);
    cudaGetSymbolAddress((void**)&p_w2q, g_w2q);
    cudaGetSymbolAddress((void**)&p_h, g_h);
    cudaGetSymbolAddress((void**)&p_b1p, g_b1p);
    cudaGetSymbolAddress((void**)&p_b2p, g_b2p);
    cudaGetSymbolAddress((void**)&p_colsum, g_colsum);
    cudaGetSymbolAddress((void**)&p_colsq, g_colsq);

    // ---- preprocessing ----
    k_prepw<<<(NP1 * KP0 + 255) / 256, 256>>>(w1_0, b1_0, DIN, DHID, KP0, NP1,
                                              p_w1h, p_w1q, p_b1p);
    k_prepw<<<(NP2 * KP2 + 255) / 256, 256>>>(w2_0, b2_0, DHID, DEMB, KP2, NP2,
                                              p_w2h, p_w2q, p_b2p);
    k_zero_pre<<<(NN + 255) / 256, 256>>>();
    k_zero_pool<<<(GG * DEMB + 255) / 256, 256>>>();
    k_edge_prep<<<(EE + 255) / 256, 256>>>(dst, edge_feats);
    k_scan1<<<SCAN_NB, 1024>>>();
    k_scan2<<<1, 128>>>();
    k_scan3<<<SCAN_NB, 1024>>>();
    k_edge_fill<<<(EE + 255) / 256, 256>>>(src, dst);
    k_counts<<<(NN + 255) / 256, 256>>>(gid);

    const int MT = (NN + BM - 1) / BM;
    dim3 grid1(MT, NP1 / 128);
    dim3 grid2a(MT, 2);
    dim3 grid2b(MT, 1);

    // ---- layer 0 ----
    k_spmm0<<<(NN * 32 + 255) / 256, 256>>>(node_feats);
    k_zero_stats<<<1, 320>>>();
    k_gemm<0, 128><<<grid1, 512, GSMEM128>>>(p_ah, p_ap, KP0, p_w1h, p_w1q, p_b1p,
                                             KP0 / BK, 0, p_th, p_tp, nullptr, nullptr, nullptr);
    k_gemm<1, 128><<<grid2a, 512, GSMEM128>>>(p_th, p_tp, KP2, p_w2h, p_w2q, p_b2p,
                                              KP2 / BK, 0, nullptr, nullptr, p_h, p_colsum, p_colsq);
    k_gemm<1, 64><<<grid2b, 512, GSMEM64>>>(p_th, p_tp, KP2, p_w2h, p_w2q, p_b2p,
                                            KP2 / BK, 256, nullptr, nullptr, p_h, p_colsum, p_colsq);
    k_bnfin<<<1, 320>>>(gamma0, beta0);

    // ---- layers 1..4 ----
    for (int l = 0; l < 4; l++) {
        k_prepw<<<(NP1 * KP1 + 255) / 256, 256>>>(w1 + (size_t)l * DEMB * DHID,
                                                  b1 + (size_t)l * DHID, DEMB, DHID, KP1, NP1,
                                                  p_w1h, p_w1q, p_b1p);
        k_prepw<<<(NP2 * KP2 + 255) / 256, 256>>>(w2 + (size_t)l * DHID * DEMB,
                                                  b2 + (size_t)l * DEMB, DHID, DEMB, KP2, NP2,
                                                  p_w2h, p_w2q, p_b2p);
        k_spmm300<<<NN, 128>>>();
        k_zero_stats<<<1, 320>>>();
        k_gemm<0, 128><<<grid1, 512, GSMEM128>>>(p_ah, p_ap, KP1, p_w1h, p_w1q, p_b1p,
                                                 KP1 / BK, 0, p_th, p_tp, nullptr, nullptr, nullptr);
        k_gemm<1, 128><<<grid2a, 512, GSMEM128>>>(p_th, p_tp, KP2, p_w2h, p_w2q, p_b2p,
                                                  KP2 / BK, 0, nullptr, nullptr, p_h, p_colsum, p_colsq);
        k_gemm<1, 64><<<grid2b, 512, GSMEM64>>>(p_th, p_tp, KP2, p_w2h, p_w2q, p_b2p,
                                                KP2 / BK, 256, nullptr, nullptr, p_h, p_colsum, p_colsq);
        k_bnfin<<<1, 320>>>(gamma + (size_t)l * DEMB, beta + (size_t)l * DEMB);
    }

    // ---- readout ----
    k_pool<<<dim3(NN / POOL_TILE, (DEMB + 127) / 128), 128>>>(gid);
    k_final<<<GG, DOUT>>>(wt, bt, out);
}

// round 8
// speedup vs baseline: 2.9032x; 1.0881x over previous
#include <cuda_runtime.h>
#include <cuda_fp16.h>
#include <math.h>
#include <stdint.h>

#define NN   100000
#define EE   1600000
#define GG   128
#define DEMB 300
#define DHID 600
#define DIN  20
#define DOUT 64
#define BN_EPS 1e-5f

#define SPLIT_S   0.015625f   // 2^-6
#define SPLIT_INV 64.0f
#define SPLIT_1MS 0.984375f   // 1 - 2^-6

// padded dims
#define KP1   320
#define KP0   64
#define NP1   640
#define KP2   640
#define NP2   320
#define HP    320

// ---------------- scratch (device globals) ----------------
__device__ __half g_h[(size_t)NN * HP];     // raw layer output, fp16 (64MB, L2-resident)
__device__ __half g_ah[(size_t)NN * KP1];   // A hi (fp16)
__device__ __half g_ap[(size_t)NN * KP1];   // A P-term
__device__ __half g_th[(size_t)NN * NP1];   // hidden hi / GEMM2 A hi
__device__ __half g_tp[(size_t)NN * NP1];
__device__ __half g_w1h[NP1 * KP1];
__device__ __half g_w1q[NP1 * KP1];
__device__ float  g_b1p[NP1];
__device__ __half g_w2h[NP2 * KP2];
__device__ __half g_w2q[NP2 * KP2];
__device__ float  g_b2p[NP2];

__device__ int   g_rowptr[NN + 1];
__device__ int   g_deg[NN];
__device__ int   g_cursor[NN];
__device__ int   g_csrc[EE];
__device__ float g_esum[NN];
__device__ int   g_blksum[128];
__device__ int   g_blkoff[128];
__device__ float g_colsum[DEMB];
__device__ float g_colsq[DEMB];
__device__ float g_a[DEMB];
__device__ float g_c[DEMB];
__device__ float g_pool[GG * DEMB];
__device__ float g_cnt[GG];

#define SCAN_NB ((NN + 1023) / 1024)

// ---------------- PTX helpers ----------------
__device__ __forceinline__ uint32_t smem_u32(const void* p) {
    uint32_t a;
    asm("{ .reg .u64 t; cvta.to.shared.u64 t, %1; cvt.u32.u64 %0, t; }" : "=r"(a) : "l"(p));
    return a;
}
__device__ __forceinline__ void cp16(uint32_t d, const void* g, bool pred) {
    int sz = pred ? 16 : 0;
    asm volatile("cp.async.cg.shared.global [%0], [%1], 16, %2;"
                 :: "r"(d), "l"(g), "r"(sz) : "memory");
}
#define CP_COMMIT() asm volatile("cp.async.commit_group;" ::: "memory")
#define CP_WAIT1()  asm volatile("cp.async.wait_group 1;" ::: "memory")

__device__ __forceinline__ void ldsm_x4(uint32_t* r, uint32_t a) {
    asm volatile("ldmatrix.sync.aligned.m8n8.x4.shared.b16 {%0,%1,%2,%3}, [%4];"
                 : "=r"(r[0]), "=r"(r[1]), "=r"(r[2]), "=r"(r[3]) : "r"(a));
}
__device__ __forceinline__ void mma_f16(float* c, const uint32_t* a, const uint32_t* b) {
    asm volatile(
        "mma.sync.aligned.m16n8k16.row.col.f32.f16.f16.f32 "
        "{%0,%1,%2,%3}, {%4,%5,%6,%7}, {%8,%9}, {%0,%1,%2,%3};"
        : "+f"(c[0]), "+f"(c[1]), "+f"(c[2]), "+f"(c[3])
        : "r"(a[0]), "r"(a[1]), "r"(a[2]), "r"(a[3]), "r"(b[0]), "r"(b[1]));
}
__device__ __forceinline__ uint32_t swz(uint32_t off) { return off ^ ((off >> 3) & 0x70); }

// producer split: hi = fp16(v), p = fp16((v-hi) + s*hi)
__device__ __forceinline__ void split2(float v, __half& h, __half& p) {
    h = __float2half_rn(v);
    float hf = __half2float(h);
    p = __float2half_rn((v - hf) + SPLIT_S * hf);
}

// ---------------- preprocessing kernels ----------------
__global__ void k_zero_pre() {
    int i = blockIdx.x * blockDim.x + threadIdx.x;
    if (i < NN) { g_deg[i] = 0; g_cursor[i] = 0; g_esum[i] = 0.f; }
}
__global__ void k_zero_pool() {
    int i = blockIdx.x * blockDim.x + threadIdx.x;
    if (i < GG * DEMB) g_pool[i] = 0.f;
    if (i < GG) g_cnt[i] = 0.f;
}
__global__ void k_zero_stats() {
    int i = threadIdx.x;
    if (i < DEMB) { g_colsum[i] = 0.f; g_colsq[i] = 0.f; }
}
__global__ void k_edge_prep(const int* __restrict__ dst, const float* __restrict__ ef) {
    int e = blockIdx.x * blockDim.x + threadIdx.x;
    if (e < EE) {
        int d = dst[e];
        atomicAdd(&g_deg[d], 1);
        atomicAdd(&g_esum[d], ef[e]);
    }
}
__global__ void k_scan1() {
    __shared__ int sh[1024];
    int b = blockIdx.x;
    int i = b * 1024 + threadIdx.x;
    int v = (i < NN) ? g_deg[i] : 0;
    sh[threadIdx.x] = v;
    __syncthreads();
#pragma unroll
    for (int off = 1; off < 1024; off <<= 1) {
        int t = (threadIdx.x >= off) ? sh[threadIdx.x - off] : 0;
        __syncthreads();
        sh[threadIdx.x] += t;
        __syncthreads();
    }
    if (i < NN) g_rowptr[i] = sh[threadIdx.x] - v;
    if (threadIdx.x == 1023) g_blksum[b] = sh[1023];
}
__global__ void k_scan2() {
    __shared__ int sh[128];
    int t = threadIdx.x;
    int v = (t < SCAN_NB) ? g_blksum[t] : 0;
    sh[t] = v;
    __syncthreads();
#pragma unroll
    for (int off = 1; off < 128; off <<= 1) {
        int x = (t >= off) ? sh[t - off] : 0;
        __syncthreads();
        sh[t] += x;
        __syncthreads();
    }
    if (t < SCAN_NB) g_blkoff[t] = sh[t] - v;
    if (t == 0) g_rowptr[NN] = EE;
}
__global__ void k_scan3() {
    int b = blockIdx.x;
    int i = b * 1024 + threadIdx.x;
    if (i < NN) g_rowptr[i] += g_blkoff[b];
}
__global__ void k_edge_fill(const int* __restrict__ src, const int* __restrict__ dst) {
    int e = blockIdx.x * blockDim.x + threadIdx.x;
    if (e < EE) {
        int d = dst[e];
        int pos = atomicAdd(&g_cursor[d], 1);
        g_csrc[g_rowptr[d] + pos] = src[e];
    }
}
__global__ void k_counts(const int* __restrict__ gid) {
    int n = blockIdx.x * blockDim.x + threadIdx.x;
    if (n < NN) atomicAdd(&g_cnt[gid[n]], 1.f);
}

// ---------------- weight prep ----------------
__global__ void k_prepw(const float* __restrict__ w, const float* __restrict__ bias,
                        int K, int Nn, int KPp, int NPp,
                        __half* __restrict__ whT, __half* __restrict__ wqT,
                        float* __restrict__ bp) {
    int idx = blockIdx.x * blockDim.x + threadIdx.x;
    if (idx >= NPp * KPp) return;
    int nrow = idx / KPp, k = idx - nrow * KPp;
    float v = (nrow < Nn && k < K) ? w[(size_t)k * Nn + nrow] : 0.f;
    __half hi = __float2half_rn(v);
    float hf = __half2float(hi);
    whT[idx] = hi;
    wqT[idx] = __float2half_rn(hf + (v - hf) * SPLIT_INV);
    if (k == 0) bp[nrow] = (nrow < Nn) ? bias[nrow] : 0.f;
}

// ---------------- SpMM kernels ----------------
__global__ void k_spmm0(const float* __restrict__ x) {
    int warp = (blockIdx.x * blockDim.x + threadIdx.x) >> 5;
    int lane = threadIdx.x & 31;
    if (warp >= NN) return;
    int beg = g_rowptr[warp], end = g_rowptr[warp + 1];
    float s = 0.f;
    for (int j = beg; j < end; j++) {
        int sn = g_csrc[j];
        if (lane < DIN) s += x[sn * DIN + lane];
    }
    float v0 = (lane < DIN) ? (s + g_esum[warp]) : 0.f;
    size_t o = (size_t)warp * KP0;
    __half h, p;
    split2(v0, h, p);
    g_ah[o + lane] = h;
    g_ap[o + lane] = p;
    g_ah[o + lane + 32] = __float2half_rn(0.f);
    g_ap[o + lane + 32] = __float2half_rn(0.f);
}

// h stored fp16 (half2 reads); BN folded; emit fp16 hi/P with pitch KP1
__global__ void k_spmm300() {
    int n = blockIdx.x;
    int t = threadIdx.x;  // 128
    int beg = g_rowptr[n], end = g_rowptr[n + 1];
    float sx = 0.f, sy = 0.f, ux = 0.f, uy = 0.f;
    const __half2* hbase = (const __half2*)g_h;
    for (int j = beg; j < end; j++) {
        const __half2* row = hbase + (size_t)g_csrc[j] * (HP / 2);
        float2 v = __half22float2(row[t]);
        sx += v.x; sy += v.y;
        if (t < 32) {
            float2 w = __half22float2(row[128 + t]);
            ux += w.x; uy += w.y;
        }
    }
    float es = g_esum[n];
    float dg = (float)(end - beg);
    size_t o = (size_t)n * KP1;
    int f = 2 * t;
    float v0 = g_a[f] * sx + dg * g_c[f] + es;
    float v1 = g_a[f + 1] * sy + dg * g_c[f + 1] + es;
    __half h0, p0, h1, p1;
    split2(v0, h0, p0);
    split2(v1, h1, p1);
    *(__half2*)(g_ah + o + f) = __halves2half2(h0, h1);
    *(__half2*)(g_ap + o + f) = __halves2half2(p0, p1);
    if (t < 32) {
        int f2 = 256 + 2 * t;
        float v2 = (f2 < DEMB)     ? (g_a[f2] * ux + dg * g_c[f2] + es) : 0.f;
        float v3 = (f2 + 1 < DEMB) ? (g_a[f2 + 1] * uy + dg * g_c[f2 + 1] + es) : 0.f;
        __half h2, p2, h3, p3;
        split2(v2, h2, p2);
        split2(v3, h3, p3);
        *(__half2*)(g_ah + o + f2) = __halves2half2(h2, h3);
        *(__half2*)(g_ap + o + f2) = __halves2half2(p2, p3);
    }
}

// ---------------- fp16 2-MMA compensated GEMM, 512 threads ----------------
// Grid: (n-tiles, m-tiles) — n-fast order for L2 A-tile reuse.
// MODE 0: bias + ReLU -> Oh/Op fp16 (pitch NP1)
// MODE 1: bias -> H fp16 (pitch HP) + column stats (cols<DEMB)
#define BM 128
#define BK 64

template <int MODE, int BNT>
__global__ __launch_bounds__(512, 1) void k_gemm(
    const __half* __restrict__ Ah, const __half* __restrict__ Ap, int KP,
    const __half* __restrict__ Bh, const __half* __restrict__ Bq,
    const float* __restrict__ biasp, int nk, int n0_base,
    __half* __restrict__ Oh, __half* __restrict__ Op,
    __half* __restrict__ H, float* __restrict__ colsum, float* __restrict__ colsq) {
    constexpr int WN_W = BNT / 32;
    constexpr int WM_W = 16 / WN_W;
    constexpr int MT_W = BM / WM_W;
    constexpr int MI   = MT_W / 16;
    constexpr int OFF_AP_ = 16384;
    constexpr int OFF_BH_ = 32768;
    constexpr int OFF_BQ_ = 32768 + BNT * 128;
    constexpr int STAGE_  = 32768 + 2 * BNT * 128;

    extern __shared__ char dyn[];
    __shared__ float s_bias[128];
    __shared__ float s_sum[128], s_sq[128];

    int tid = threadIdx.x;
    int wid = tid >> 5;
    int lane = tid & 31;
    int wm = wid / WN_W;
    int wn = wid % WN_W;
    int m0 = blockIdx.y * BM;                  // m on y (slow)
    int n0 = n0_base + blockIdx.x * BNT;       // n on x (fast)

    uint32_t dynb0 = smem_u32(dyn);
    uint32_t dynb = (dynb0 + 1023u) & ~1023u;

    if (tid < BNT) {
        s_bias[tid] = biasp[n0 + tid];
        if (MODE == 1) { s_sum[tid] = 0.f; s_sq[tid] = 0.f; }
    }

    float acc1[MI][4][4] = {};
    float acc2[MI][4][4] = {};

    auto load_stage = [&](int s, int kt) {
        uint32_t ab = dynb + s * STAGE_;
        int k0 = kt * BK;
#pragma unroll
        for (int it = 0; it < 4; it++) {
            int i = tid + it * 512;
            int var = i >> 10;
            int j = i & 1023;
            int r = j >> 3, sg = j & 7;
            const __half* base = var ? Ap : Ah;
            const void* g = base + (size_t)(m0 + r) * KP + k0 + sg * 8;
            uint32_t d = ab + (var ? OFF_AP_ : 0) + swz((uint32_t)(r * 128 + sg * 16));
            cp16(d, g, (m0 + r) < NN);
        }
#pragma unroll
        for (int it = 0; it < BNT * 16 / 512; it++) {
            int i = tid + it * 512;
            int var = i / (BNT * 8);
            int j = i % (BNT * 8);
            int r = j >> 3, sg = j & 7;
            const __half* base = var ? Bq : Bh;
            const void* g = base + (size_t)(n0 + r) * KP + k0 + sg * 8;
            uint32_t d = ab + (var ? OFF_BQ_ : OFF_BH_) + swz((uint32_t)(r * 128 + sg * 16));
            cp16(d, g, true);
        }
    };

    int lr = lane & 15;
    int lc = ((lane >> 4) & 1) * 16;

    auto compute = [&](int s) {
        uint32_t ab = dynb + s * STAGE_;
#pragma unroll
        for (int ks = 0; ks < 4; ks++) {
            int kb = ks * 32;
            uint32_t ah[MI][4], ap[MI][4];
#pragma unroll
            for (int mi = 0; mi < MI; mi++) {
                uint32_t off = swz((uint32_t)((wm * MT_W + mi * 16 + lr) * 128 + kb + lc));
                ldsm_x4(ah[mi], ab + off);
                ldsm_x4(ap[mi], ab + OFF_AP_ + off);
            }
            uint32_t bh[2][4], bq[2][4];
#pragma unroll
            for (int bi = 0; bi < 2; bi++) {
                uint32_t off = swz((uint32_t)((wn * 32 + bi * 16 + lr) * 128 + kb + lc));
                ldsm_x4(bh[bi], ab + OFF_BH_ + off);
                ldsm_x4(bq[bi], ab + OFF_BQ_ + off);
            }
#pragma unroll
            for (int mi = 0; mi < MI; mi++) {
#pragma unroll
                for (int t = 0; t < 4; t++) {
                    uint32_t bfh[2] = { bh[t >> 1][t & 1], bh[t >> 1][(t & 1) + 2] };
                    uint32_t bfq[2] = { bq[t >> 1][t & 1], bq[t >> 1][(t & 1) + 2] };
                    mma_f16(acc1[mi][t], ah[mi], bfh);
                    mma_f16(acc2[mi][t], ap[mi], bfq);
                }
            }
        }
    };

    load_stage(0, 0);
    CP_COMMIT();
    if (nk > 1) load_stage(1, 1);
    CP_COMMIT();
    for (int kt = 0; kt < nk; kt++) {
        CP_WAIT1();
        __syncthreads();
        if (kt + 2 < nk) load_stage((kt + 2) % 3, kt + 2);
        CP_COMMIT();
        compute(kt % 3);
    }

    // ---------------- epilogue ----------------
    int lrow = lane >> 2;
    int lcol = (lane & 3) * 2;

    if (MODE == 0) {
#pragma unroll
        for (int mi = 0; mi < MI; mi++) {
            int gm = m0 + wm * MT_W + mi * 16 + lrow;
#pragma unroll
            for (int t = 0; t < 4; t++) {
                int c = wn * 32 + t * 8 + lcol;
                float b0 = s_bias[c], b1 = s_bias[c + 1];
                int cg = n0 + c;
#pragma unroll
                for (int rr = 0; rr < 2; rr++) {
                    int g = gm + rr * 8;
                    if (g < NN) {
                        float v0 = fmaxf(SPLIT_1MS * acc1[mi][t][rr * 2 + 0] +
                                         acc2[mi][t][rr * 2 + 0] + b0, 0.f);
                        float v1 = fmaxf(SPLIT_1MS * acc1[mi][t][rr * 2 + 1] +
                                         acc2[mi][t][rr * 2 + 1] + b1, 0.f);
                        __half h0, p0, h1, p1;
                        split2(v0, h0, p0);
                        split2(v1, h1, p1);
                        uint32_t hp = (uint32_t)__half_as_ushort(h0) |
                                      ((uint32_t)__half_as_ushort(h1) << 16);
                        uint32_t pp = (uint32_t)__half_as_ushort(p0) |
                                      ((uint32_t)__half_as_ushort(p1) << 16);
                        *(uint32_t*)(Oh + (size_t)g * NP1 + cg) = hp;
                        *(uint32_t*)(Op + (size_t)g * NP1 + cg) = pp;
                    }
                }
            }
        }
    } else {
#pragma unroll
        for (int t = 0; t < 4; t++) {
            int c = wn * 32 + t * 8 + lcol;
            int cg = n0 + c;
            float b0 = s_bias[c], b1 = s_bias[c + 1];
            float s0 = 0.f, s1 = 0.f, q0 = 0.f, q1 = 0.f;
#pragma unroll
            for (int mi = 0; mi < MI; mi++) {
                int gm = m0 + wm * MT_W + mi * 16 + lrow;
                float v0 = SPLIT_1MS * acc1[mi][t][0] + acc2[mi][t][0] + b0;
                float v1 = SPLIT_1MS * acc1[mi][t][1] + acc2[mi][t][1] + b1;
                float v2 = SPLIT_1MS * acc1[mi][t][2] + acc2[mi][t][2] + b0;
                float v3 = SPLIT_1MS * acc1[mi][t][3] + acc2[mi][t][3] + b1;
                if (gm >= NN) { v0 = 0.f; v1 = 0.f; }
                if (gm + 8 >= NN) { v2 = 0.f; v3 = 0.f; }
                if (cg < HP) {
                    if (gm < NN)
                        *(__half2*)(H + (size_t)gm * HP + cg) = __floats2half2_rn(v0, v1);
                    if (gm + 8 < NN)
                        *(__half2*)(H + (size_t)(gm + 8) * HP + cg) = __floats2half2_rn(v2, v3);
                }
                s0 += v0 + v2; s1 += v1 + v3;
                q0 += v0 * v0 + v2 * v2; q1 += v1 * v1 + v3 * v3;
            }
#pragma unroll
            for (int off = 4; off < 32; off <<= 1) {
                s0 += __shfl_xor_sync(0xffffffffu, s0, off);
                s1 += __shfl_xor_sync(0xffffffffu, s1, off);
                q0 += __shfl_xor_sync(0xffffffffu, q0, off);
                q1 += __shfl_xor_sync(0xffffffffu, q1, off);
            }
            if (lane < 4) {
                if (cg < DEMB) { atomicAdd(&s_sum[c], s0); atomicAdd(&s_sq[c], q0); }
                if (cg + 1 < DEMB) { atomicAdd(&s_sum[c + 1], s1); atomicAdd(&s_sq[c + 1], q1); }
            }
        }
        __syncthreads();
        if (tid < BNT) {
            int n = n0 + tid;
            if (n < DEMB) {
                atomicAdd(&colsum[n], s_sum[tid]);
                atomicAdd(&colsq[n], s_sq[tid]);
            }
        }
    }
}

// ---------------- BN finalize ----------------
__global__ void k_bnfin(const float* __restrict__ gamma, const float* __restrict__ beta) {
    int f = threadIdx.x;
    if (f >= DEMB) return;
    const float invM = 1.0f / (float)NN;
    float mu = g_colsum[f] * invM;
    float var = g_colsq[f] * invM - mu * mu;
    float a = gamma[f] * rsqrtf(var + BN_EPS);
    g_a[f] = a;
    g_c[f] = beta[f] - mu * a;
}

// ---------------- pooling (reads fp16 h) ----------------
#define POOL_TILE 32
__global__ void k_pool(const int* __restrict__ gid) {
    int f = blockIdx.y * 128 + threadIdx.x;
    if (f >= DEMB) return;
    int n0 = blockIdx.x * POOL_TILE;
    float acc = 0.f;
    int cur = gid[n0];
    for (int i = 0; i < POOL_TILE; i++) {
        int n = n0 + i;
        int g = gid[n];
        if (g != cur) {
            atomicAdd(&g_pool[cur * DEMB + f], acc);
            acc = 0.f;
            cur = g;
        }
        acc += __half2float(g_h[(size_t)n * HP + f]);
    }
    atomicAdd(&g_pool[cur * DEMB + f], acc);
}

// ---------------- final ----------------
__global__ void k_final(const float* __restrict__ wt, const float* __restrict__ bt,
                        float* __restrict__ out) {
    int g = blockIdx.x;
    int o = threadIdx.x;
    float cnt = g_cnt[g];
    float inv = 1.0f / fmaxf(cnt, 1.f);
    float acc = 0.f;
    for (int f = 0; f < DEMB; f++) {
        float pf = (g_a[f] * g_pool[g * DEMB + f] + cnt * g_c[f]) * inv;
        acc += pf * wt[f * DOUT + o];
    }
    out[g * DOUT + o] = acc + bt[o];
}

// ---------------- host launcher ----------------
#define GSMEM128 (3 * (32768 + 2 * 128 * 128) + 1024)
#define GSMEM64  (3 * (32768 + 2 * 64 * 128) + 1024)

extern "C" void kernel_launch(void* const* d_in, const int* in_sizes, int n_in,
                              void* d_out, int out_size) {
    const float* node_feats = (const float*)d_in[0];
    const float* edge_feats = (const float*)d_in[1];
    const int*   src        = (const int*)d_in[2];
    const int*   dst        = (const int*)d_in[3];
    const int*   gid        = (const int*)d_in[4];
    const float* w1_0  = (const float*)d_in[5];
    const float* b1_0  = (const float*)d_in[6];
    const float* w2_0  = (const float*)d_in[7];
    const float* b2_0  = (const float*)d_in[8];
    const float* gamma0 = (const float*)d_in[9];
    const float* beta0  = (const float*)d_in[10];
    const float* w1   = (const float*)d_in[11];
    const float* b1   = (const float*)d_in[12];
    const float* w2   = (const float*)d_in[13];
    const float* b2   = (const float*)d_in[14];
    const float* gamma = (const float*)d_in[15];
    const float* beta  = (const float*)d_in[16];
    const float* wt   = (const float*)d_in[17];
    const float* bt   = (const float*)d_in[18];
    float* out = (float*)d_out;

    static bool attr_done = false;
    if (!attr_done) {
        cudaFuncSetAttribute(k_gemm<0, 128>, cudaFuncAttributeMaxDynamicSharedMemorySize, GSMEM128);
        cudaFuncSetAttribute(k_gemm<1, 128>, cudaFuncAttributeMaxDynamicSharedMemorySize, GSMEM128);
        cudaFuncSetAttribute(k_gemm<1, 64>,  cudaFuncAttributeMaxDynamicSharedMemorySize, GSMEM64);
        attr_done = true;
    }

    __half *p_ah, *p_ap, *p_th, *p_tp, *p_w1h, *p_w1q, *p_w2h, *p_w2q, *p_h;
    float *p_b1p, *p_b2p, *p_colsum, *p_colsq;
    cudaGetSymbolAddress((void**)&p_ah, g_ah);
    cudaGetSymbolAddress((void**)&p_ap, g_ap);
    cudaGetSymbolAddress((void**)&p_th, g_th);
    cudaGetSymbolAddress((void**)&p_tp, g_tp);
    cudaGetSymbolAddress((void**)&p_w1h, g_w1h);
    cudaGetSymbolAddress((void**)&p_w1q, g_w1q);
    cudaGetSymbolAddress((void**)&p_w2h, g_w2h);
    cudaGetSymbolAddress((void**)&p_w2q, g_w2q);
    cudaGetSymbolAddress((void**)&p_h, g_h);
    cudaGetSymbolAddress((void**)&p_b1p, g_b1p);
    cudaGetSymbolAddress((void**)&p_b2p, g_b2p);
    cudaGetSymbolAddress((void**)&p_colsum, g_colsum);
    cudaGetSymbolAddress((void**)&p_colsq, g_colsq);

    // ---- preprocessing ----
    k_prepw<<<(NP1 * KP0 + 255) / 256, 256>>>(w1_0, b1_0, DIN, DHID, KP0, NP1,
                                              p_w1h, p_w1q, p_b1p);
    k_prepw<<<(NP2 * KP2 + 255) / 256, 256>>>(w2_0, b2_0, DHID, DEMB, KP2, NP2,
                                              p_w2h, p_w2q, p_b2p);
    k_zero_pre<<<(NN + 255) / 256, 256>>>();
    k_zero_pool<<<(GG * DEMB + 255) / 256, 256>>>();
    k_edge_prep<<<(EE + 255) / 256, 256>>>(dst, edge_feats);
    k_scan1<<<SCAN_NB, 1024>>>();
    k_scan2<<<1, 128>>>();
    k_scan3<<<SCAN_NB, 1024>>>();
    k_edge_fill<<<(EE + 255) / 256, 256>>>(src, dst);
    k_counts<<<(NN + 255) / 256, 256>>>(gid);

    const int MT = (NN + BM - 1) / BM;
    dim3 grid1(NP1 / 128, MT);    // n-fast
    dim3 grid2a(2, MT);
    dim3 grid2b(1, MT);

    // ---- layer 0 ----
    k_spmm0<<<(NN * 32 + 255) / 256, 256>>>(node_feats);
    k_zero_stats<<<1, 320>>>();
    k_gemm<0, 128><<<grid1, 512, GSMEM128>>>(p_ah, p_ap, KP0, p_w1h, p_w1q, p_b1p,
                                             KP0 / BK, 0, p_th, p_tp, nullptr, nullptr, nullptr);
    k_gemm<1, 128><<<grid2a, 512, GSMEM128>>>(p_th, p_tp, KP2, p_w2h, p_w2q, p_b2p,
                                              KP2 / BK, 0, nullptr, nullptr, p_h, p_colsum, p_colsq);
    k_gemm<1, 64><<<grid2b, 512, GSMEM64>>>(p_th, p_tp, KP2, p_w2h, p_w2q, p_b2p,
                                            KP2 / BK, 256, nullptr, nullptr, p_h, p_colsum, p_colsq);
    k_bnfin<<<1, 320>>>(gamma0, beta0);

    // ---- layers 1..4 ----
    for (int l = 0; l < 4; l++) {
        k_prepw<<<(NP1 * KP1 + 255) / 256, 256>>>(w1 + (size_t)l * DEMB * DHID,
                                                  b1 + (size_t)l * DHID, DEMB, DHID, KP1, NP1,
                                                  p_w1h, p_w1q, p_b1p);
        k_prepw<<<(NP2 * KP2 + 255) / 256, 256>>>(w2 + (size_t)l * DHID * DEMB,
                                                  b2 + (size_t)l * DEMB, DHID, DEMB, KP2, NP2,
                                                  p_w2h, p_w2q, p_b2p);
        k_spmm300<<<NN, 128>>>();
        k_zero_stats<<<1, 320>>>();
        k_gemm<0, 128><<<grid1, 512, GSMEM128>>>(p_ah, p_ap, KP1, p_w1h, p_w1q, p_b1p,
                                                 KP1 / BK, 0, p_th, p_tp, nullptr, nullptr, nullptr);
        k_gemm<1, 128><<<grid2a, 512, GSMEM128>>>(p_th, p_tp, KP2, p_w2h, p_w2q, p_b2p,
                                                  KP2 / BK, 0, nullptr, nullptr, p_h, p_colsum, p_colsq);
        k_gemm<1, 64><<<grid2b, 512, GSMEM64>>>(p_th, p_tp, KP2, p_w2h, p_w2q, p_b2p,
                                                KP2 / BK, 256, nullptr, nullptr, p_h, p_colsum, p_colsq);
        k_bnfin<<<1, 320>>>(gamma + (size_t)l * DEMB, beta + (size_t)l * DEMB);
    }

    // ---- readout ----
    k_pool<<<dim3(NN / POOL_TILE, (DEMB + 127) / 128), 128>>>(gid);
    k_final<<<GG, DOUT>>>(wt, bt, out);
}

// round 9
// speedup vs baseline: 2.9991x; 1.0330x over previous
#include <cuda_runtime.h>
#include <cuda_fp16.h>
#include <math.h>
#include <stdint.h>

#define NN   100000
#define EE   1600000
#define GG   128
#define DEMB 300
#define DHID 600
#define DIN  20
#define DOUT 64
#define BN_EPS 1e-5f

#define SPLIT_S   0.015625f   // 2^-6
#define SPLIT_INV 64.0f
#define SPLIT_1MS 0.984375f   // 1 - 2^-6

// padded dims
#define KP1   320
#define KP0   64
#define NP1   640
#define KP2   640
#define NP2   320
#define HP    320

// ---------------- scratch (device globals) ----------------
__device__ __half g_h[(size_t)NN * HP];     // raw layer output, fp16 (64MB, L2-resident)
__device__ __half g_ah[(size_t)NN * KP1];   // A hi (fp16)
__device__ __half g_ap[(size_t)NN * KP1];   // A P-term
__device__ __half g_th[(size_t)NN * NP1];   // hidden hi / GEMM2 A hi
__device__ __half g_tp[(size_t)NN * NP1];
__device__ __half g_w1h[NP1 * KP1];
__device__ __half g_w1q[NP1 * KP1];
__device__ float  g_b1p[NP1];
__device__ __half g_w2h[NP2 * KP2];
__device__ __half g_w2q[NP2 * KP2];
__device__ float  g_b2p[NP2];

__device__ int   g_rowptr[NN + 1];
__device__ int   g_deg[NN];
__device__ int   g_cursor[NN];
__device__ int   g_csrc[EE];
__device__ float g_esum[NN];
__device__ int   g_blksum[128];
__device__ int   g_blkoff[128];
__device__ float g_colsum[DEMB];
__device__ float g_colsq[DEMB];
__device__ float g_a[DEMB];
__device__ float g_c[DEMB];
__device__ float g_pool[GG * DEMB];
__device__ float g_cnt[GG];

#define SCAN_NB ((NN + 1023) / 1024)

// ---------------- PTX helpers ----------------
__device__ __forceinline__ uint32_t smem_u32(const void* p) {
    uint32_t a;
    asm("{ .reg .u64 t; cvta.to.shared.u64 t, %1; cvt.u32.u64 %0, t; }" : "=r"(a) : "l"(p));
    return a;
}
__device__ __forceinline__ void cp16(uint32_t d, const void* g, bool pred) {
    int sz = pred ? 16 : 0;
    asm volatile("cp.async.cg.shared.global [%0], [%1], 16, %2;"
                 :: "r"(d), "l"(g), "r"(sz) : "memory");
}
#define CP_COMMIT() asm volatile("cp.async.commit_group;" ::: "memory")
#define CP_WAIT1()  asm volatile("cp.async.wait_group 1;" ::: "memory")

__device__ __forceinline__ void ldsm_x4(uint32_t* r, uint32_t a) {
    asm volatile("ldmatrix.sync.aligned.m8n8.x4.shared.b16 {%0,%1,%2,%3}, [%4];"
                 : "=r"(r[0]), "=r"(r[1]), "=r"(r[2]), "=r"(r[3]) : "r"(a));
}
__device__ __forceinline__ void mma_f16(float* c, const uint32_t* a, const uint32_t* b) {
    asm volatile(
        "mma.sync.aligned.m16n8k16.row.col.f32.f16.f16.f32 "
        "{%0,%1,%2,%3}, {%4,%5,%6,%7}, {%8,%9}, {%0,%1,%2,%3};"
        : "+f"(c[0]), "+f"(c[1]), "+f"(c[2]), "+f"(c[3])
        : "r"(a[0]), "r"(a[1]), "r"(a[2]), "r"(a[3]), "r"(b[0]), "r"(b[1]));
}
__device__ __forceinline__ uint32_t swz(uint32_t off) { return off ^ ((off >> 3) & 0x70); }

// producer split: hi = fp16(v), p = fp16((v-hi) + s*hi)
__device__ __forceinline__ void split2(float v, __half& h, __half& p) {
    h = __float2half_rn(v);
    float hf = __half2float(h);
    p = __float2half_rn((v - hf) + SPLIT_S * hf);
}

// ---------------- preprocessing kernels ----------------
__global__ void k_zero_pre() {
    int i = blockIdx.x * blockDim.x + threadIdx.x;
    if (i < NN) { g_deg[i] = 0; g_cursor[i] = 0; g_esum[i] = 0.f; }
}
__global__ void k_zero_pool() {
    int i = blockIdx.x * blockDim.x + threadIdx.x;
    if (i < GG * DEMB) g_pool[i] = 0.f;
    if (i < GG) g_cnt[i] = 0.f;
}
__global__ void k_zero_stats() {
    int i = threadIdx.x;
    if (i < DEMB) { g_colsum[i] = 0.f; g_colsq[i] = 0.f; }
}
__global__ void k_edge_prep(const int* __restrict__ dst, const float* __restrict__ ef) {
    int e = blockIdx.x * blockDim.x + threadIdx.x;
    if (e < EE) {
        int d = dst[e];
        atomicAdd(&g_deg[d], 1);
        atomicAdd(&g_esum[d], ef[e]);
    }
}
__global__ void k_scan1() {
    __shared__ int sh[1024];
    int b = blockIdx.x;
    int i = b * 1024 + threadIdx.x;
    int v = (i < NN) ? g_deg[i] : 0;
    sh[threadIdx.x] = v;
    __syncthreads();
#pragma unroll
    for (int off = 1; off < 1024; off <<= 1) {
        int t = (threadIdx.x >= off) ? sh[threadIdx.x - off] : 0;
        __syncthreads();
        sh[threadIdx.x] += t;
        __syncthreads();
    }
    if (i < NN) g_rowptr[i] = sh[threadIdx.x] - v;
    if (threadIdx.x == 1023) g_blksum[b] = sh[1023];
}
__global__ void k_scan2() {
    __shared__ int sh[128];
    int t = threadIdx.x;
    int v = (t < SCAN_NB) ? g_blksum[t] : 0;
    sh[t] = v;
    __syncthreads();
#pragma unroll
    for (int off = 1; off < 128; off <<= 1) {
        int x = (t >= off) ? sh[t - off] : 0;
        __syncthreads();
        sh[t] += x;
        __syncthreads();
    }
    if (t < SCAN_NB) g_blkoff[t] = sh[t] - v;
    if (t == 0) g_rowptr[NN] = EE;
}
__global__ void k_scan3() {
    int b = blockIdx.x;
    int i = b * 1024 + threadIdx.x;
    if (i < NN) g_rowptr[i] += g_blkoff[b];
}
__global__ void k_edge_fill(const int* __restrict__ src, const int* __restrict__ dst) {
    int e = blockIdx.x * blockDim.x + threadIdx.x;
    if (e < EE) {
        int d = dst[e];
        int pos = atomicAdd(&g_cursor[d], 1);
        g_csrc[g_rowptr[d] + pos] = src[e];
    }
}
__global__ void k_counts(const int* __restrict__ gid) {
    int n = blockIdx.x * blockDim.x + threadIdx.x;
    if (n < NN) atomicAdd(&g_cnt[gid[n]], 1.f);
}

// ---------------- weight prep ----------------
__global__ void k_prepw(const float* __restrict__ w, const float* __restrict__ bias,
                        int K, int Nn, int KPp, int NPp,
                        __half* __restrict__ whT, __half* __restrict__ wqT,
                        float* __restrict__ bp) {
    int idx = blockIdx.x * blockDim.x + threadIdx.x;
    if (idx >= NPp * KPp) return;
    int nrow = idx / KPp, k = idx - nrow * KPp;
    float v = (nrow < Nn && k < K) ? w[(size_t)k * Nn + nrow] : 0.f;
    __half hi = __float2half_rn(v);
    float hf = __half2float(hi);
    whT[idx] = hi;
    wqT[idx] = __float2half_rn(hf + (v - hf) * SPLIT_INV);
    if (k == 0) bp[nrow] = (nrow < Nn) ? bias[nrow] : 0.f;
}

// ---------------- SpMM kernels ----------------
__global__ void k_spmm0(const float* __restrict__ x) {
    int warp = (blockIdx.x * blockDim.x + threadIdx.x) >> 5;
    int lane = threadIdx.x & 31;
    if (warp >= NN) return;
    int beg = g_rowptr[warp], end = g_rowptr[warp + 1];
    float s = 0.f;
    for (int j = beg; j < end; j++) {
        int sn = g_csrc[j];
        if (lane < DIN) s += x[sn * DIN + lane];
    }
    float v0 = (lane < DIN) ? (s + g_esum[warp]) : 0.f;
    size_t o = (size_t)warp * KP0;
    __half h, p;
    split2(v0, h, p);
    g_ah[o + lane] = h;
    g_ap[o + lane] = p;
    g_ah[o + lane + 32] = __float2half_rn(0.f);
    g_ap[o + lane + 32] = __float2half_rn(0.f);
}

// h stored fp16 (half2 reads); BN folded; emit fp16 hi/P with pitch KP1
__global__ void k_spmm300() {
    int n = blockIdx.x;
    int t = threadIdx.x;  // 128
    int beg = g_rowptr[n], end = g_rowptr[n + 1];
    float sx = 0.f, sy = 0.f, ux = 0.f, uy = 0.f;
    const __half2* hbase = (const __half2*)g_h;
    for (int j = beg; j < end; j++) {
        const __half2* row = hbase + (size_t)g_csrc[j] * (HP / 2);
        float2 v = __half22float2(row[t]);
        sx += v.x; sy += v.y;
        if (t < 32) {
            float2 w = __half22float2(row[128 + t]);
            ux += w.x; uy += w.y;
        }
    }
    float es = g_esum[n];
    float dg = (float)(end - beg);
    size_t o = (size_t)n * KP1;
    int f = 2 * t;
    float v0 = g_a[f] * sx + dg * g_c[f] + es;
    float v1 = g_a[f + 1] * sy + dg * g_c[f + 1] + es;
    __half h0, p0, h1, p1;
    split2(v0, h0, p0);
    split2(v1, h1, p1);
    *(__half2*)(g_ah + o + f) = __halves2half2(h0, h1);
    *(__half2*)(g_ap + o + f) = __halves2half2(p0, p1);
    if (t < 32) {
        int f2 = 256 + 2 * t;
        float v2 = (f2 < DEMB)     ? (g_a[f2] * ux + dg * g_c[f2] + es) : 0.f;
        float v3 = (f2 + 1 < DEMB) ? (g_a[f2 + 1] * uy + dg * g_c[f2 + 1] + es) : 0.f;
        __half h2, p2, h3, p3;
        split2(v2, h2, p2);
        split2(v3, h3, p3);
        *(__half2*)(g_ah + o + f2) = __halves2half2(h2, h3);
        *(__half2*)(g_ap + o + f2) = __halves2half2(p2, p3);
    }
}

// ---------------- fp16 2-MMA compensated GEMM, 256 threads / 8 warps ----------------
// Warp tile 64x32 (BNT=128: 2m x 4n, MI=4) for higher MMA:LDSM ratio (2.67 vs 2.0).
// Grid: (n-tiles, m-tiles) — n-fast order for L2 A-tile reuse.
// MODE 0: bias + ReLU -> Oh/Op fp16 (pitch NP1)
// MODE 1: bias -> H fp16 (pitch HP) + column stats (cols<DEMB)
#define BM 128
#define BK 64
#define GTHREADS 256
#define NWARPS 8

template <int MODE, int BNT>
__global__ __launch_bounds__(GTHREADS, 1) void k_gemm(
    const __half* __restrict__ Ah, const __half* __restrict__ Ap, int KP,
    const __half* __restrict__ Bh, const __half* __restrict__ Bq,
    const float* __restrict__ biasp, int nk, int n0_base,
    __half* __restrict__ Oh, __half* __restrict__ Op,
    __half* __restrict__ H, float* __restrict__ colsum, float* __restrict__ colsq) {
    constexpr int WN_W = BNT / 32;            // warps along n (4 or 2)
    constexpr int WM_W = NWARPS / WN_W;       // warps along m (2 or 4)
    constexpr int MT_W = BM / WM_W;           // rows per warp (64 or 32)
    constexpr int MI   = MT_W / 16;           // 16-row chunks (4 or 2)
    constexpr int OFF_AP_ = 16384;
    constexpr int OFF_BH_ = 32768;
    constexpr int OFF_BQ_ = 32768 + BNT * 128;
    constexpr int STAGE_  = 32768 + 2 * BNT * 128;

    extern __shared__ char dyn[];
    __shared__ float s_bias[128];
    __shared__ float s_sum[128], s_sq[128];

    int tid = threadIdx.x;
    int wid = tid >> 5;
    int lane = tid & 31;
    int wm = wid / WN_W;
    int wn = wid % WN_W;
    int m0 = blockIdx.y * BM;                  // m on y (slow)
    int n0 = n0_base + blockIdx.x * BNT;       // n on x (fast)

    uint32_t dynb0 = smem_u32(dyn);
    uint32_t dynb = (dynb0 + 1023u) & ~1023u;

    if (tid < BNT) {
        s_bias[tid] = biasp[n0 + tid];
        if (MODE == 1) { s_sum[tid] = 0.f; s_sq[tid] = 0.f; }
    }

    float acc1[MI][4][4] = {};
    float acc2[MI][4][4] = {};

    auto load_stage = [&](int s, int kt) {
        uint32_t ab = dynb + s * STAGE_;
        int k0 = kt * BK;
#pragma unroll
        for (int it = 0; it < 2048 / GTHREADS; it++) {   // A hi+lo: 2048 cp16
            int i = tid + it * GTHREADS;
            int var = i >> 10;
            int j = i & 1023;
            int r = j >> 3, sg = j & 7;
            const __half* base = var ? Ap : Ah;
            const void* g = base + (size_t)(m0 + r) * KP + k0 + sg * 8;
            uint32_t d = ab + (var ? OFF_AP_ : 0) + swz((uint32_t)(r * 128 + sg * 16));
            cp16(d, g, (m0 + r) < NN);
        }
#pragma unroll
        for (int it = 0; it < BNT * 16 / GTHREADS; it++) {   // B hi+lo
            int i = tid + it * GTHREADS;
            int var = i / (BNT * 8);
            int j = i % (BNT * 8);
            int r = j >> 3, sg = j & 7;
            const __half* base = var ? Bq : Bh;
            const void* g = base + (size_t)(n0 + r) * KP + k0 + sg * 8;
            uint32_t d = ab + (var ? OFF_BQ_ : OFF_BH_) + swz((uint32_t)(r * 128 + sg * 16));
            cp16(d, g, true);
        }
    };

    int lr = lane & 15;
    int lc = ((lane >> 4) & 1) * 16;

    auto compute = [&](int s) {
        uint32_t ab = dynb + s * STAGE_;
#pragma unroll
        for (int ks = 0; ks < 4; ks++) {
            int kb = ks * 32;
            uint32_t ah[MI][4], ap[MI][4];
#pragma unroll
            for (int mi = 0; mi < MI; mi++) {
                uint32_t off = swz((uint32_t)((wm * MT_W + mi * 16 + lr) * 128 + kb + lc));
                ldsm_x4(ah[mi], ab + off);
                ldsm_x4(ap[mi], ab + OFF_AP_ + off);
            }
            uint32_t bh[2][4], bq[2][4];
#pragma unroll
            for (int bi = 0; bi < 2; bi++) {
                uint32_t off = swz((uint32_t)((wn * 32 + bi * 16 + lr) * 128 + kb + lc));
                ldsm_x4(bh[bi], ab + OFF_BH_ + off);
                ldsm_x4(bq[bi], ab + OFF_BQ_ + off);
            }
#pragma unroll
            for (int mi = 0; mi < MI; mi++) {
#pragma unroll
                for (int t = 0; t < 4; t++) {
                    uint32_t bfh[2] = { bh[t >> 1][t & 1], bh[t >> 1][(t & 1) + 2] };
                    uint32_t bfq[2] = { bq[t >> 1][t & 1], bq[t >> 1][(t & 1) + 2] };
                    mma_f16(acc1[mi][t], ah[mi], bfh);
                    mma_f16(acc2[mi][t], ap[mi], bfq);
                }
            }
        }
    };

    load_stage(0, 0);
    CP_COMMIT();
    if (nk > 1) load_stage(1, 1);
    CP_COMMIT();
    for (int kt = 0; kt < nk; kt++) {
        CP_WAIT1();
        __syncthreads();
        if (kt + 2 < nk) load_stage((kt + 2) % 3, kt + 2);
        CP_COMMIT();
        compute(kt % 3);
    }

    // ---------------- epilogue ----------------
    int lrow = lane >> 2;
    int lcol = (lane & 3) * 2;

    if (MODE == 0) {
#pragma unroll
        for (int mi = 0; mi < MI; mi++) {
            int gm = m0 + wm * MT_W + mi * 16 + lrow;
#pragma unroll
            for (int t = 0; t < 4; t++) {
                int c = wn * 32 + t * 8 + lcol;
                float b0 = s_bias[c], b1 = s_bias[c + 1];
                int cg = n0 + c;
#pragma unroll
                for (int rr = 0; rr < 2; rr++) {
                    int g = gm + rr * 8;
                    if (g < NN) {
                        float v0 = fmaxf(SPLIT_1MS * acc1[mi][t][rr * 2 + 0] +
                                         acc2[mi][t][rr * 2 + 0] + b0, 0.f);
                        float v1 = fmaxf(SPLIT_1MS * acc1[mi][t][rr * 2 + 1] +
                                         acc2[mi][t][rr * 2 + 1] + b1, 0.f);
                        __half h0, p0, h1, p1;
                        split2(v0, h0, p0);
                        split2(v1, h1, p1);
                        uint32_t hp = (uint32_t)__half_as_ushort(h0) |
                                      ((uint32_t)__half_as_ushort(h1) << 16);
                        uint32_t pp = (uint32_t)__half_as_ushort(p0) |
                                      ((uint32_t)__half_as_ushort(p1) << 16);
                        *(uint32_t*)(Oh + (size_t)g * NP1 + cg) = hp;
                        *(uint32_t*)(Op + (size_t)g * NP1 + cg) = pp;
                    }
                }
            }
        }
    } else {
#pragma unroll
        for (int t = 0; t < 4; t++) {
            int c = wn * 32 + t * 8 + lcol;
            int cg = n0 + c;
            float b0 = s_bias[c], b1 = s_bias[c + 1];
            float s0 = 0.f, s1 = 0.f, q0 = 0.f, q1 = 0.f;
#pragma unroll
            for (int mi = 0; mi < MI; mi++) {
                int gm = m0 + wm * MT_W + mi * 16 + lrow;
                float v0 = SPLIT_1MS * acc1[mi][t][0] + acc2[mi][t][0] + b0;
                float v1 = SPLIT_1MS * acc1[mi][t][1] + acc2[mi][t][1] + b1;
                float v2 = SPLIT_1MS * acc1[mi][t][2] + acc2[mi][t][2] + b0;
                float v3 = SPLIT_1MS * acc1[mi][t][3] + acc2[mi][t][3] + b1;
                if (gm >= NN) { v0 = 0.f; v1 = 0.f; }
                if (gm + 8 >= NN) { v2 = 0.f; v3 = 0.f; }
                if (cg < HP) {
                    if (gm < NN)
                        *(__half2*)(H + (size_t)gm * HP + cg) = __floats2half2_rn(v0, v1);
                    if (gm + 8 < NN)
                        *(__half2*)(H + (size_t)(gm + 8) * HP + cg) = __floats2half2_rn(v2, v3);
                }
                s0 += v0 + v2; s1 += v1 + v3;
                q0 += v0 * v0 + v2 * v2; q1 += v1 * v1 + v3 * v3;
            }
#pragma unroll
            for (int off = 4; off < 32; off <<= 1) {
                s0 += __shfl_xor_sync(0xffffffffu, s0, off);
                s1 += __shfl_xor_sync(0xffffffffu, s1, off);
                q0 += __shfl_xor_sync(0xffffffffu, q0, off);
                q1 += __shfl_xor_sync(0xffffffffu, q1, off);
            }
            if (lane < 4) {
                if (cg < DEMB) { atomicAdd(&s_sum[c], s0); atomicAdd(&s_sq[c], q0); }
                if (cg + 1 < DEMB) { atomicAdd(&s_sum[c + 1], s1); atomicAdd(&s_sq[c + 1], q1); }
            }
        }
        __syncthreads();
        if (tid < BNT) {
            int n = n0 + tid;
            if (n < DEMB) {
                atomicAdd(&colsum[n], s_sum[tid]);
                atomicAdd(&colsq[n], s_sq[tid]);
            }
        }
    }
}

// ---------------- BN finalize ----------------
__global__ void k_bnfin(const float* __restrict__ gamma, const float* __restrict__ beta) {
    int f = threadIdx.x;
    if (f >= DEMB) return;
    const float invM = 1.0f / (float)NN;
    float mu = g_colsum[f] * invM;
    float var = g_colsq[f] * invM - mu * mu;
    float a = gamma[f] * rsqrtf(var + BN_EPS);
    g_a[f] = a;
    g_c[f] = beta[f] - mu * a;
}

// ---------------- pooling (reads fp16 h) ----------------
#define POOL_TILE 32
__global__ void k_pool(const int* __restrict__ gid) {
    int f = blockIdx.y * 128 + threadIdx.x;
    if (f >= DEMB) return;
    int n0 = blockIdx.x * POOL_TILE;
    float acc = 0.f;
    int cur = gid[n0];
    for (int i = 0; i < POOL_TILE; i++) {
        int n = n0 + i;
        int g = gid[n];
        if (g != cur) {
            atomicAdd(&g_pool[cur * DEMB + f], acc);
            acc = 0.f;
            cur = g;
        }
        acc += __half2float(g_h[(size_t)n * HP + f]);
    }
    atomicAdd(&g_pool[cur * DEMB + f], acc);
}

// ---------------- final ----------------
__global__ void k_final(const float* __restrict__ wt, const float* __restrict__ bt,
                        float* __restrict__ out) {
    int g = blockIdx.x;
    int o = threadIdx.x;
    float cnt = g_cnt[g];
    float inv = 1.0f / fmaxf(cnt, 1.f);
    float acc = 0.f;
    for (int f = 0; f < DEMB; f++) {
        float pf = (g_a[f] * g_pool[g * DEMB + f] + cnt * g_c[f]) * inv;
        acc += pf * wt[f * DOUT + o];
    }
    out[g * DOUT + o] = acc + bt[o];
}

// ---------------- host launcher ----------------
#define GSMEM128 (3 * (32768 + 2 * 128 * 128) + 1024)
#define GSMEM64  (3 * (32768 + 2 * 64 * 128) + 1024)

extern "C" void kernel_launch(void* const* d_in, const int* in_sizes, int n_in,
                              void* d_out, int out_size) {
    const float* node_feats = (const float*)d_in[0];
    const float* edge_feats = (const float*)d_in[1];
    const int*   src        = (const int*)d_in[2];
    const int*   dst        = (const int*)d_in[3];
    const int*   gid        = (const int*)d_in[4];
    const float* w1_0  = (const float*)d_in[5];
    const float* b1_0  = (const float*)d_in[6];
    const float* w2_0  = (const float*)d_in[7];
    const float* b2_0  = (const float*)d_in[8];
    const float* gamma0 = (const float*)d_in[9];
    const float* beta0  = (const float*)d_in[10];
    const float* w1   = (const float*)d_in[11];
    const float* b1   = (const float*)d_in[12];
    const float* w2   = (const float*)d_in[13];
    const float* b2   = (const float*)d_in[14];
    const float* gamma = (const float*)d_in[15];
    const float* beta  = (const float*)d_in[16];
    const float* wt   = (const float*)d_in[17];
    const float* bt   = (const float*)d_in[18];
    float* out = (float*)d_out;

    static bool attr_done = false;
    if (!attr_done) {
        cudaFuncSetAttribute(k_gemm<0, 128>, cudaFuncAttributeMaxDynamicSharedMemorySize, GSMEM128);
        cudaFuncSetAttribute(k_gemm<1, 128>, cudaFuncAttributeMaxDynamicSharedMemorySize, GSMEM128);
        cudaFuncSetAttribute(k_gemm<1, 64>,  cudaFuncAttributeMaxDynamicSharedMemorySize, GSMEM64);
        attr_done = true;
    }

    __half *p_ah, *p_ap, *p_th, *p_tp, *p_w1h, *p_w1q, *p_w2h, *p_w2q, *p_h;
    float *p_b1p, *p_b2p, *p_colsum, *p_colsq;
    cudaGetSymbolAddress((void**)&p_ah, g_ah);
    cudaGetSymbolAddress((void**)&p_ap, g_ap);
    cudaGetSymbolAddress((void**)&p_th, g_th);
    cudaGetSymbolAddress((void**)&p_tp, g_tp);
    cudaGetSymbolAddress((void**)&p_w1h, g_w1h);
    cudaGetSymbolAddress((void**)&p_w1q, g_w1q);
    cudaGetSymbolAddress((void**)&p_w2h, g_w2h);
    cudaGetSymbolAddress((void**)&p_w2q, g_w2q);
    cudaGetSymbolAddress((void**)&p_h, g_h);
    cudaGetSymbolAddress((void**)&p_b1p, g_b1p);
    cudaGetSymbolAddress((void**)&p_b2p, g_b2p);
    cudaGetSymbolAddress((void**)&p_colsum, g_colsum);
    cudaGetSymbolAddress((void**)&p_colsq, g_colsq);

    // ---- preprocessing ----
    k_prepw<<<(NP1 * KP0 + 255) / 256, 256>>>(w1_0, b1_0, DIN, DHID, KP0, NP1,
                                              p_w1h, p_w1q, p_b1p);
    k_prepw<<<(NP2 * KP2 + 255) / 256, 256>>>(w2_0, b2_0, DHID, DEMB, KP2, NP2,
                                              p_w2h, p_w2q, p_b2p);
    k_zero_pre<<<(NN + 255) / 256, 256>>>();
    k_zero_pool<<<(GG * DEMB + 255) / 256, 256>>>();
    k_edge_prep<<<(EE + 255) / 256, 256>>>(dst, edge_feats);
    k_scan1<<<SCAN_NB, 1024>>>();
    k_scan2<<<1, 128>>>();
    k_scan3<<<SCAN_NB, 1024>>>();
    k_edge_fill<<<(EE + 255) / 256, 256>>>(src, dst);
    k_counts<<<(NN + 255) / 256, 256>>>(gid);

    const int MT = (NN + BM - 1) / BM;
    dim3 grid1(NP1 / 128, MT);    // n-fast
    dim3 grid2a(2, MT);
    dim3 grid2b(1, MT);

    // ---- layer 0 ----
    k_spmm0<<<(NN * 32 + 255) / 256, 256>>>(node_feats);
    k_zero_stats<<<1, 320>>>();
    k_gemm<0, 128><<<grid1, GTHREADS, GSMEM128>>>(p_ah, p_ap, KP0, p_w1h, p_w1q, p_b1p,
                                                  KP0 / BK, 0, p_th, p_tp, nullptr, nullptr, nullptr);
    k_gemm<1, 128><<<grid2a, GTHREADS, GSMEM128>>>(p_th, p_tp, KP2, p_w2h, p_w2q, p_b2p,
                                                   KP2 / BK, 0, nullptr, nullptr, p_h, p_colsum, p_colsq);
    k_gemm<1, 64><<<grid2b, GTHREADS, GSMEM64>>>(p_th, p_tp, KP2, p_w2h, p_w2q, p_b2p,
                                                 KP2 / BK, 256, nullptr, nullptr, p_h, p_colsum, p_colsq);
    k_bnfin<<<1, 320>>>(gamma0, beta0);

    // ---- layers 1..4 ----
    for (int l = 0; l < 4; l++) {
        k_prepw<<<(NP1 * KP1 + 255) / 256, 256>>>(w1 + (size_t)l * DEMB * DHID,
                                                  b1 + (size_t)l * DHID, DEMB, DHID, KP1, NP1,
                                                  p_w1h, p_w1q, p_b1p);
        k_prepw<<<(NP2 * KP2 + 255) / 256, 256>>>(w2 + (size_t)l * DHID * DEMB,
                                                  b2 + (size_t)l * DEMB, DHID, DEMB, KP2, NP2,
                                                  p_w2h, p_w2q, p_b2p);
        k_spmm300<<<NN, 128>>>();
        k_zero_stats<<<1, 320>>>();
        k_gemm<0, 128><<<grid1, GTHREADS, GSMEM128>>>(p_ah, p_ap, KP1, p_w1h, p_w1q, p_b1p,
                                                      KP1 / BK, 0, p_th, p_tp, nullptr, nullptr, nullptr);
        k_gemm<1, 128><<<grid2a, GTHREADS, GSMEM128>>>(p_th, p_tp, KP2, p_w2h, p_w2q, p_b2p,
                                                       KP2 / BK, 0, nullptr, nullptr, p_h, p_colsum, p_colsq);
        k_gemm<1, 64><<<grid2b, GTHREADS, GSMEM64>>>(p_th, p_tp, KP2, p_w2h, p_w2q, p_b2p,
                                                     KP2 / BK, 256, nullptr, nullptr, p_h, p_colsum, p_colsq);
        k_bnfin<<<1, 320>>>(gamma + (size_t)l * DEMB, beta + (size_t)l * DEMB);
    }

    // ---- readout ----
    k_pool<<<dim3(NN / POOL_TILE, (DEMB + 127) / 128), 128>>>(gid);
    k_final<<<GG, DOUT>>>(wt, bt, out);
}